// round 8
// baseline (speedup 1.0000x reference)
#include <cuda_runtime.h>
#include <cstdint>

#define BB 4
#define IC 256
#define NN 4096
#define HW 16384

// ---- scratch ----
__device__ __align__(16) float g_XT[BB*NN*IC];   // x^T   [b][n][c]
__device__ __align__(16) float g_TH[BB*NN*IC];   // theta [b][n][c]
__device__ __align__(16) float g_PH[BB*NN*IC];   // phi   [b][n][c]
__device__ __align__(16) float g_GX[BB*IC*NN];   // g     [b][o][n]  (V for attn)
__device__ __align__(16) float g_GN[BB*NN*IC];   // g     [b][n][o]  (A for y_c)
__device__ __align__(16) float g_YS[BB*NN*IC];   // y_s   [b][n][o]
__device__ __align__(16) float g_FCP[BB*8*IC*IC];
__device__ __align__(16) float g_FC[BB*IC*IC];   // f_c^T [b][d][c]
__device__ __align__(16) float g_YC[BB*NN*IC];   // y_c   [b][n][d]
__device__ __align__(16) float g_Z [BB*64*HW];
__device__ __align__(16) float g_H [BB*16*HW];

static __device__ __forceinline__ uint32_t smem_u32(const void* p) {
    uint32_t a;
    asm("{ .reg .u64 t; cvta.to.shared.u64 t, %1; cvt.u32.u64 %0, t; }" : "=r"(a) : "l"(p));
    return a;
}
static __device__ __forceinline__ void mma8(float* d, const uint32_t* a, const uint32_t* b) {
    asm volatile(
        "mma.sync.aligned.m16n8k8.row.col.f32.tf32.tf32.f32 "
        "{%0,%1,%2,%3}, {%4,%5,%6,%7}, {%8,%9}, {%0,%1,%2,%3};"
        : "+f"(d[0]), "+f"(d[1]), "+f"(d[2]), "+f"(d[3])
        : "r"(a[0]), "r"(a[1]), "r"(a[2]), "r"(a[3]), "r"(b[0]), "r"(b[1]));
}
#define CPA(dst, src) asm volatile("cp.async.cg.shared.global [%0], [%1], 16;" :: "r"(dst), "l"(src))
#define CPC() asm volatile("cp.async.commit_group;" ::: "memory")
#define CPW0() asm volatile("cp.async.wait_group 0;" ::: "memory")

// ============================================================
// warp-MMA tf32 GEMM (cp.async double-buffered):
// D[bx*128..][by*128..] = A @ B^T; A [M][K] ldA, B [N][K] ldB, K%32==0
// mode 0: +aux[col]; 1: +aux[row]; else plain
// ============================================================
__global__ __launch_bounds__(256, 2) void wgemm(
    const float* __restrict__ A, int ldA, size_t Abs,
    const float* __restrict__ B, int ldB, size_t Bbs,
    float* __restrict__ D, int ldD, size_t Dbs,
    int K, const float* __restrict__ aux, int mode)
{
    extern __shared__ __align__(16) char wsm[];   // A: [2][128][36] @0, B @36864
    const uint32_t sb = smem_u32(wsm);
    const uint32_t* uS = (const uint32_t*)wsm;
    const int tid = threadIdx.x, wid = tid >> 5, lane = tid & 31;
    const int gid = lane >> 2, tig = lane & 3;
    const int wm = wid & 3, wn = wid >> 2;
    const float* At = A + (size_t)blockIdx.z*Abs + (size_t)blockIdx.x*128*ldA;
    const float* Bt = B + (size_t)blockIdx.z*Bbs + (size_t)blockIdx.y*128*ldB;
    float acc[2][8][4] = {};
    const int NC = K >> 5;

    #pragma unroll
    for (int l = 0; l < 4; l++) {
        int f = l*256 + tid, r = f >> 3, c4 = (f & 7)*4;
        CPA(sb + (uint32_t)(r*36 + c4)*4, At + (size_t)r*ldA + c4);
        CPA(sb + 36864u + (uint32_t)(r*36 + c4)*4, Bt + (size_t)r*ldB + c4);
    }
    CPC();

    #pragma unroll 1
    for (int kc = 0; kc < NC; kc++) {
        CPW0();
        __syncthreads();
        if (kc + 1 < NC) {
            const int ko = (kc + 1)*32;
            const uint32_t bo = (uint32_t)((kc + 1) & 1)*18432u;
            #pragma unroll
            for (int l = 0; l < 4; l++) {
                int f = l*256 + tid, r = f >> 3, c4 = (f & 7)*4;
                CPA(sb + bo + (uint32_t)(r*36 + c4)*4, At + (size_t)r*ldA + ko + c4);
                CPA(sb + 36864u + bo + (uint32_t)(r*36 + c4)*4, Bt + (size_t)r*ldB + ko + c4);
            }
            CPC();
        }
        const uint32_t* uA = uS + (kc & 1)*4608;
        const uint32_t* uB = uS + 9216 + (kc & 1)*4608;
        #pragma unroll
        for (int ks = 0; ks < 4; ks++) {
            const int kk = ks*8;
            uint32_t af[2][4], bf[8][2];
            #pragma unroll
            for (int i = 0; i < 2; i++) {
                const int rb = wm*32 + i*16;
                af[i][0] = uA[(rb+gid)*36 + kk+tig];
                af[i][1] = uA[(rb+8+gid)*36 + kk+tig];
                af[i][2] = uA[(rb+gid)*36 + kk+tig+4];
                af[i][3] = uA[(rb+8+gid)*36 + kk+tig+4];
            }
            #pragma unroll
            for (int j = 0; j < 8; j++) {
                const int nb = wn*64 + j*8 + gid;
                bf[j][0] = uB[nb*36 + kk+tig];
                bf[j][1] = uB[nb*36 + kk+tig+4];
            }
            #pragma unroll
            for (int i = 0; i < 2; i++)
                #pragma unroll
                for (int j = 0; j < 8; j++)
                    mma8(acc[i][j], af[i], bf[j]);
        }
    }

    float* Dt = D + (size_t)blockIdx.z*Dbs + (size_t)blockIdx.x*128*ldD + blockIdx.y*128;
    #pragma unroll
    for (int i = 0; i < 2; i++) {
        const int r0 = wm*32 + i*16 + gid, r1 = r0 + 8;
        float add0 = 0.f, add1 = 0.f;
        if (mode == 1) {
            add0 = aux[blockIdx.x*128 + r0];
            add1 = aux[blockIdx.x*128 + r1];
        }
        #pragma unroll
        for (int j = 0; j < 8; j++) {
            const int cl = wn*64 + j*8 + 2*tig;
            float v0 = acc[i][j][0], v1 = acc[i][j][1];
            float v2 = acc[i][j][2], v3 = acc[i][j][3];
            if (mode == 0) {
                const int cg = blockIdx.y*128 + cl;
                float a0 = __ldg(&aux[cg]), a1 = __ldg(&aux[cg+1]);
                v0 += a0; v1 += a1; v2 += a0; v3 += a1;
            } else if (mode == 1) {
                v0 += add0; v1 += add0; v2 += add1; v3 += add1;
            }
            *(float2*)(Dt + (size_t)r0*ldD + cl) = make_float2(v0, v1);
            *(float2*)(Dt + (size_t)r1*ldD + cl) = make_float2(v2, v3);
        }
    }
}

// ============================================================
// fused flash attention (tf32 HMMA, no max rescale — logits bounded):
// y_s[q][o] = softmax_m(TH[q]·PH[m]) @ GX^T, grid (32 qtiles, 4 b)
// SMEM: Q [128][256] xor-swz @0; P [128][128] @131072; KV 2x[128][32] @196608
// ============================================================
__global__ __launch_bounds__(256, 1) void attn_kernel()
{
    extern __shared__ __align__(16) char asmm[];
    uint32_t* SQ = (uint32_t*)asmm;
    uint32_t* SP = (uint32_t*)(asmm + 131072);
    uint32_t* SV = (uint32_t*)(asmm + 196608);
    __shared__ float sLp[2][128];
    const uint32_t sb = smem_u32(asmm);
    const int tid = threadIdx.x, wid = tid >> 5, lane = tid & 31;
    const int gid = lane >> 2, tig = lane & 3;
    const int wm = wid & 3, wn = wid >> 2, swg = gid << 2;
    const int b = blockIdx.y, q0 = blockIdx.x*128;

    if (tid < 128) { sLp[0][tid] = 0.f; sLp[1][tid] = 0.f; }

    const float* Qp = g_TH + ((size_t)b*NN + q0)*IC;
    #pragma unroll
    for (int l = 0; l < 32; l++) {
        int f = l*256 + tid, r = f >> 6, c4 = (f & 63)*4;
        CPA(sb + (uint32_t)(r*256 + (c4 ^ ((r & 7) << 2)))*4, Qp + (size_t)r*IC + c4);
    }
    CPC();

    float oacc[2][2][8][4] = {};

    #pragma unroll 1
    for (int m0 = 0; m0 < NN; m0 += 128) {
        const float* Kp = g_PH + ((size_t)b*NN + m0)*IC;
        __syncthreads();
        #pragma unroll
        for (int l = 0; l < 4; l++) {
            int f = l*256 + tid, r = f >> 3, c4 = (f & 7)*4;
            CPA(sb + 196608u + (uint32_t)(r*32 + (c4 ^ ((r & 7) << 2)))*4,
                Kp + (size_t)r*IC + c4);
        }
        CPC();
        float sacc[2][8][4] = {};
        #pragma unroll 1
        for (int cc = 0; cc < 8; cc++) {
            CPW0();
            __syncthreads();
            if (cc < 7) {
                const float* Kn = Kp + (cc + 1)*32;
                const uint32_t dst = sb + 196608u + (uint32_t)((cc + 1) & 1)*16384u;
                #pragma unroll
                for (int l = 0; l < 4; l++) {
                    int f = l*256 + tid, r = f >> 3, c4 = (f & 7)*4;
                    CPA(dst + (uint32_t)(r*32 + (c4 ^ ((r & 7) << 2)))*4,
                        Kn + (size_t)r*IC + c4);
                }
                CPC();
            }
            const uint32_t* SVc = SV + (cc & 1)*4096;
            #pragma unroll
            for (int ks = 0; ks < 4; ks++) {
                const int kk = ks*8;
                uint32_t af[2][4], bf[8][2];
                const int ca = cc*32 + kk + tig;
                #pragma unroll
                for (int i = 0; i < 2; i++) {
                    const int rb = wm*32 + i*16 + gid;
                    af[i][0] = SQ[rb*256 + (ca ^ swg)];
                    af[i][1] = SQ[(rb+8)*256 + (ca ^ swg)];
                    af[i][2] = SQ[rb*256 + ((ca+4) ^ swg)];
                    af[i][3] = SQ[(rb+8)*256 + ((ca+4) ^ swg)];
                }
                #pragma unroll
                for (int j = 0; j < 8; j++) {
                    const int nb = wn*64 + j*8 + gid;
                    bf[j][0] = SVc[nb*32 + ((kk+tig) ^ swg)];
                    bf[j][1] = SVc[nb*32 + ((kk+tig+4) ^ swg)];
                }
                #pragma unroll
                for (int i = 0; i < 2; i++)
                    #pragma unroll
                    for (int j = 0; j < 8; j++)
                        mma8(sacc[i][j], af[i], bf[j]);
            }
        }
        // exp -> P (raw fp32 bits; HMMA truncates to tf32), accumulate row sums
        #pragma unroll
        for (int i = 0; i < 2; i++) {
            const int r0 = wm*32 + i*16 + gid, r1 = r0 + 8;
            float ls0 = 0.f, ls1 = 0.f;
            #pragma unroll
            for (int j = 0; j < 8; j++) {
                const int cl = wn*64 + j*8 + 2*tig;
                float v0 = __expf(sacc[i][j][0]), v1 = __expf(sacc[i][j][1]);
                float v2 = __expf(sacc[i][j][2]), v3 = __expf(sacc[i][j][3]);
                ls0 += v0 + v1; ls1 += v2 + v3;
                const int p0 = r0*128 + (cl ^ swg), p1 = r1*128 + (cl ^ swg);
                SP[p0] = __float_as_uint(v0); SP[p0+1] = __float_as_uint(v1);
                SP[p1] = __float_as_uint(v2); SP[p1+1] = __float_as_uint(v3);
            }
            ls0 += __shfl_xor_sync(0xffffffffu, ls0, 1);
            ls0 += __shfl_xor_sync(0xffffffffu, ls0, 2);
            ls1 += __shfl_xor_sync(0xffffffffu, ls1, 1);
            ls1 += __shfl_xor_sync(0xffffffffu, ls1, 2);
            if (tig == 0) { sLp[wn][r0] += ls0; sLp[wn][r1] += ls1; }
        }
        __syncthreads();
        // PV: 8 sub-steps (vc over 4 key-subchunks, oh over 2 o-halves)
        {
            const float* Vp = g_GX + (size_t)b*IC*NN + m0;
            #pragma unroll
            for (int l = 0; l < 4; l++) {
                int f = l*256 + tid, r = f >> 3, c4 = (f & 7)*4;
                CPA(sb + 196608u + (uint32_t)(r*32 + (c4 ^ ((r & 7) << 2)))*4,
                    Vp + (size_t)r*NN + c4);
            }
            CPC();
        }
        #pragma unroll 1
        for (int st = 0; st < 8; st++) {
            const int vc = st >> 1, oh = st & 1;
            CPW0();
            __syncthreads();
            if (st < 7) {
                const int vn = (st + 1) >> 1, on = (st + 1) & 1;
                const float* Vp = g_GX + ((size_t)b*IC + on*128)*NN + m0 + vn*32;
                const uint32_t dst = sb + 196608u + (uint32_t)((st + 1) & 1)*16384u;
                #pragma unroll
                for (int l = 0; l < 4; l++) {
                    int f = l*256 + tid, r = f >> 3, c4 = (f & 7)*4;
                    CPA(dst + (uint32_t)(r*32 + (c4 ^ ((r & 7) << 2)))*4,
                        Vp + (size_t)r*NN + c4);
                }
                CPC();
            }
            const uint32_t* SVc = SV + (st & 1)*4096;
            #pragma unroll
            for (int ks = 0; ks < 4; ks++) {
                const int kk = ks*8;
                uint32_t af[2][4], bf[8][2];
                const int ca = vc*32 + kk + tig;
                #pragma unroll
                for (int i = 0; i < 2; i++) {
                    const int rb = wm*32 + i*16 + gid;
                    af[i][0] = SP[rb*128 + (ca ^ swg)];
                    af[i][1] = SP[(rb+8)*128 + (ca ^ swg)];
                    af[i][2] = SP[rb*128 + ((ca+4) ^ swg)];
                    af[i][3] = SP[(rb+8)*128 + ((ca+4) ^ swg)];
                }
                #pragma unroll
                for (int j = 0; j < 8; j++) {
                    const int nb = wn*64 + j*8 + gid;
                    bf[j][0] = SVc[nb*32 + ((kk+tig) ^ swg)];
                    bf[j][1] = SVc[nb*32 + ((kk+tig+4) ^ swg)];
                }
                #pragma unroll
                for (int i = 0; i < 2; i++)
                    #pragma unroll
                    for (int j = 0; j < 8; j++)
                        mma8(oacc[oh][i][j], af[i], bf[j]);
            }
        }
    }
    __syncthreads();
    float* Yp = g_YS + ((size_t)b*NN + q0)*IC;
    #pragma unroll
    for (int i = 0; i < 2; i++) {
        const int r0 = wm*32 + i*16 + gid, r1 = r0 + 8;
        const float inv0 = 1.f/(sLp[0][r0] + sLp[1][r0]);
        const float inv1 = 1.f/(sLp[0][r1] + sLp[1][r1]);
        #pragma unroll
        for (int oh = 0; oh < 2; oh++)
            #pragma unroll
            for (int j = 0; j < 8; j++) {
                const int cl = oh*128 + wn*64 + j*8 + 2*tig;
                *(float2*)(Yp + (size_t)r0*IC + cl) =
                    make_float2(oacc[oh][i][j][0]*inv0, oacc[oh][i][j][1]*inv0);
                *(float2*)(Yp + (size_t)r1*IC + cl) =
                    make_float2(oacc[oh][i][j][2]*inv1, oacc[oh][i][j][3]*inv1);
            }
    }
}

// x[b][c][n] -> g_XT[b][n][c]; grid (128, 8, 4), block (32,8)
__global__ __launch_bounds__(256) void transpose_kernel(const float* __restrict__ x)
{
    __shared__ float t[32][33];
    const int b = blockIdx.z, n0 = blockIdx.x*32, c0 = blockIdx.y*32;
    const int tx = threadIdx.x, ty = threadIdx.y;
    #pragma unroll
    for (int i = 0; i < 4; i++)
        t[ty + i*8][tx] = x[(size_t)b*IC*NN + (size_t)(c0 + ty + i*8)*NN + n0 + tx];
    __syncthreads();
    #pragma unroll
    for (int i = 0; i < 4; i++)
        g_XT[(size_t)b*NN*IC + (size_t)(n0 + ty + i*8)*IC + c0 + tx] = t[tx][ty + i*8];
}

// f_c partials, split-K x8: grid (4,4,32=b*8+ks)
__global__ __launch_bounds__(256) void fcgemm_kernel()
{
    __shared__ __align__(16) float sA[32][68], sB[32][68];
    const int c0 = blockIdx.x*64, d0 = blockIdx.y*64;
    const int bz = blockIdx.z, b = bz >> 3, ks = bz & 7;
    const int tid = threadIdx.x, tx = tid & 15, ty = tid >> 4;
    const float* TH = g_TH + (size_t)b*NN*IC + (size_t)ks*512*IC;
    const float* PH = g_PH + (size_t)b*NN*IC + (size_t)ks*512*IC;
    float acc[4][4] = {};
    for (int n0 = 0; n0 < 512; n0 += 32) {
        #pragma unroll
        for (int l = 0; l < 8; l++) {
            int idx = l*256 + tid, ki = idx >> 6, ci = idx & 63;
            sA[ki][ci] = TH[(size_t)(n0 + ki)*IC + c0 + ci];
            sB[ki][ci] = PH[(size_t)(n0 + ki)*IC + d0 + ci];
        }
        __syncthreads();
        #pragma unroll
        for (int k = 0; k < 32; k++) {
            float a[4];
            #pragma unroll
            for (int i = 0; i < 4; i++) a[i] = sA[k][4*ty + i];
            float4 bv = *(const float4*)&sB[k][4*tx];
            float bb[4] = {bv.x, bv.y, bv.z, bv.w};
            #pragma unroll
            for (int i = 0; i < 4; i++)
                #pragma unroll
                for (int j = 0; j < 4; j++) acc[i][j] += a[i]*bb[j];
        }
        __syncthreads();
    }
    float* FCP = g_FCP + (size_t)bz*IC*IC;
    #pragma unroll
    for (int i = 0; i < 4; i++)
        #pragma unroll
        for (int j = 0; j < 4; j++)
            FCP[(c0 + 4*ty + i)*IC + d0 + 4*tx + j] = acc[i][j];
}

// reduce split-K + softmax over d; writes TRANSPOSED f_c^T[d][c]; grid (256,4)
__global__ __launch_bounds__(256) void fcsoftmax_kernel()
{
    __shared__ float red[256];
    const int b = blockIdx.y, c = blockIdx.x, tid = threadIdx.x;
    float v = 0.f;
    #pragma unroll
    for (int ks = 0; ks < 8; ks++)
        v += g_FCP[(((size_t)b*8 + ks)*IC + c)*IC + tid];
    red[tid] = v; __syncthreads();
    for (int s = 128; s > 0; s >>= 1) {
        if (tid < s) red[tid] = fmaxf(red[tid], red[tid + s]);
        __syncthreads();
    }
    float m = red[0]; __syncthreads();
    float e = __expf(v - m);
    red[tid] = e; __syncthreads();
    for (int s = 128; s > 0; s >>= 1) {
        if (tid < s) red[tid] += red[tid + s];
        __syncthreads();
    }
    g_FC[(size_t)b*IC*IC + (size_t)tid*IC + c] = e / red[0];
}

// z = x + gs*(Ws@ys+b) + gc*(Wc@yc+b); grid (256,4)
__global__ __launch_bounds__(256) void zmix_kernel(
    const float* __restrict__ x,
    const float* __restrict__ Ws_w, const float* __restrict__ Ws_b,
    const float* __restrict__ Wc_w, const float* __restrict__ Wc_b,
    const float* __restrict__ gs, const float* __restrict__ gc,
    float* __restrict__ zout)
{
    __shared__ float sW[64][64];
    __shared__ float sD[64][65];
    const int b = blockIdx.y, p0 = blockIdx.x*64;
    const int tid = threadIdx.x, tx = tid & 63, ty = tid >> 6;
    float accs[16] = {}, accc[16] = {};
    #pragma unroll
    for (int l = 0; l < 16; l++) {
        int idx = l*256 + tid;
        sW[idx >> 6][idx & 63] = Ws_w[idx];
        int i = idx >> 6, px = idx & 63;
        int p = p0 + px, h = p >> 7, w = p & 127;
        int o = 4*i + (h >> 5), n = ((h & 31) << 7) | w;
        sD[i][px] = g_YS[((size_t)(b << 12) + n)*IC + o];
    }
    __syncthreads();
    #pragma unroll 4
    for (int i = 0; i < 64; i++) {
        float yv = sD[i][tx];
        #pragma unroll
        for (int k = 0; k < 16; k++) accs[k] += sW[16*ty + k][i]*yv;
    }
    __syncthreads();
    #pragma unroll
    for (int l = 0; l < 16; l++) {
        int idx = l*256 + tid;
        sW[idx >> 6][idx & 63] = Wc_w[idx];
        int i = idx >> 6, px = idx & 63;
        int p = p0 + px, h = p >> 7, w = p & 127;
        int n = (i << 6) + (h >> 1), d = ((h & 1) << 7) | w;
        sD[i][px] = g_YC[((size_t)(b << 12) + n)*IC + d];
    }
    __syncthreads();
    #pragma unroll 4
    for (int i = 0; i < 64; i++) {
        float cv = sD[i][tx];
        #pragma unroll
        for (int k = 0; k < 16; k++) accc[k] += sW[16*ty + k][i]*cv;
    }
    float gsv = gs[0], gcv = gc[0];
    int p = p0 + tx;
    #pragma unroll
    for (int k = 0; k < 16; k++) {
        int oc = 16*ty + k;
        size_t idx = (size_t)(b*64 + oc)*HW + p;
        float z = x[idx] + gsv*(accs[k] + Ws_b[oc]) + gcv*(accc[k] + Wc_b[oc]);
        g_Z[idx] = z;
        zout[idx] = z;
    }
}

// conv3x3 64->16 + relu; grid (4,16,4), block (32,8)
__global__ __launch_bounds__(256) void conv1_kernel(
    const float* __restrict__ m1w, const float* __restrict__ m1b)
{
    __shared__ float sw[16*64*9];
    __shared__ float st[10][36];
    const int b = blockIdx.z, h0 = blockIdx.y*8, w0 = blockIdx.x*32;
    const int tx = threadIdx.x, ty = threadIdx.y, tid = ty*32 + tx;
    for (int i = tid; i < 9216; i += 256) sw[i] = m1w[i];
    float acc[16];
    #pragma unroll
    for (int oc = 0; oc < 16; oc++) acc[oc] = m1b[oc];
    for (int ic = 0; ic < 64; ic++) {
        const float* zp = g_Z + (size_t)(b*64 + ic)*HW;
        __syncthreads();
        for (int l = tid; l < 340; l += 256) {
            int yy = l / 34, xx = l % 34;
            int hh = h0 - 1 + yy, ww = w0 - 1 + xx;
            st[yy][xx] = (hh >= 0 && hh < 128 && ww >= 0 && ww < 128) ? zp[hh*128 + ww] : 0.f;
        }
        __syncthreads();
        #pragma unroll
        for (int dy = 0; dy < 3; dy++)
            #pragma unroll
            for (int dx = 0; dx < 3; dx++) {
                float zv = st[ty + dy][tx + dx];
                #pragma unroll
                for (int oc = 0; oc < 16; oc++)
                    acc[oc] += sw[(oc*64 + ic)*9 + dy*3 + dx]*zv;
            }
    }
    int h = h0 + ty, w = w0 + tx;
    #pragma unroll
    for (int oc = 0; oc < 16; oc++)
        g_H[(size_t)(b*16 + oc)*HW + h*128 + w] = fmaxf(acc[oc], 0.f);
}

// conv3x3 16->1; grid (4,16,4), block (32,8)
__global__ __launch_bounds__(256) void conv2_kernel(
    const float* __restrict__ m2w, const float* __restrict__ m2b,
    float* __restrict__ out)
{
    __shared__ float sw[144];
    __shared__ float st[10][36];
    const int b = blockIdx.z, h0 = blockIdx.y*8, w0 = blockIdx.x*32;
    const int tx = threadIdx.x, ty = threadIdx.y, tid = ty*32 + tx;
    if (tid < 144) sw[tid] = m2w[tid];
    float acc = m2b[0];
    for (int ic = 0; ic < 16; ic++) {
        const float* hp = g_H + (size_t)(b*16 + ic)*HW;
        __syncthreads();
        for (int l = tid; l < 340; l += 256) {
            int yy = l / 34, xx = l % 34;
            int hh = h0 - 1 + yy, ww = w0 - 1 + xx;
            st[yy][xx] = (hh >= 0 && hh < 128 && ww >= 0 && ww < 128) ? hp[hh*128 + ww] : 0.f;
        }
        __syncthreads();
        #pragma unroll
        for (int dy = 0; dy < 3; dy++)
            #pragma unroll
            for (int dx = 0; dx < 3; dx++)
                acc += sw[ic*9 + dy*3 + dx]*st[ty + dy][tx + dx];
    }
    out[(size_t)b*HW + (h0 + ty)*128 + (w0 + tx)] = acc;
}

extern "C" void kernel_launch(void* const* d_in, const int* in_sizes, int n_in,
                              void* d_out, int out_size)
{
    const float* x    = (const float*)d_in[0];
    const float* g_w  = (const float*)d_in[1];
    const float* g_b  = (const float*)d_in[2];
    const float* th_w = (const float*)d_in[3];
    const float* th_b = (const float*)d_in[4];
    const float* ph_w = (const float*)d_in[5];
    const float* ph_b = (const float*)d_in[6];
    const float* Ws_w = (const float*)d_in[7];
    const float* Ws_b = (const float*)d_in[8];
    const float* Wc_w = (const float*)d_in[9];
    const float* Wc_b = (const float*)d_in[10];
    const float* gs   = (const float*)d_in[11];
    const float* gc   = (const float*)d_in[12];
    const float* m1w  = (const float*)d_in[13];
    const float* m1b  = (const float*)d_in[14];
    const float* m2w  = (const float*)d_in[15];
    const float* m2b  = (const float*)d_in[16];
    float* out = (float*)d_out;   // logit [4*16384] then z [4*64*16384]

    cudaFuncSetAttribute(wgemm, cudaFuncAttributeMaxDynamicSharedMemorySize, 73728);
    cudaFuncSetAttribute(attn_kernel, cudaFuncAttributeMaxDynamicSharedMemorySize, 229376);

    float *XT, *TH, *PH, *GX, *GN, *YS, *FC, *YC;
    cudaGetSymbolAddress((void**)&XT, g_XT);
    cudaGetSymbolAddress((void**)&TH, g_TH);
    cudaGetSymbolAddress((void**)&PH, g_PH);
    cudaGetSymbolAddress((void**)&GX, g_GX);
    cudaGetSymbolAddress((void**)&GN, g_GN);
    cudaGetSymbolAddress((void**)&YS, g_YS);
    cudaGetSymbolAddress((void**)&FC, g_FC);
    cudaGetSymbolAddress((void**)&YC, g_YC);

    transpose_kernel<<<dim3(128, 8, 4), dim3(32, 8)>>>(x);

    // theta [n][c] = XT @ th_w^T + bias(col)
    wgemm<<<dim3(32, 2, 4), 256, 73728>>>(XT, IC, (size_t)NN*IC,
        th_w, IC, 0, TH, IC, (size_t)NN*IC, IC, th_b, 0);
    // phi
    wgemm<<<dim3(32, 2, 4), 256, 73728>>>(XT, IC, (size_t)NN*IC,
        ph_w, IC, 0, PH, IC, (size_t)NN*IC, IC, ph_b, 0);
    // g [o][n] = g_w @ XT^T + bias(row)
    wgemm<<<dim3(2, 32, 4), 256, 73728>>>(g_w, IC, 0,
        XT, IC, (size_t)NN*IC, GX, NN, (size_t)IC*NN, IC, g_b, 1);
    // g [n][o] = XT @ g_w^T + bias(col)
    wgemm<<<dim3(32, 2, 4), 256, 73728>>>(XT, IC, (size_t)NN*IC,
        g_w, IC, 0, GN, IC, (size_t)NN*IC, IC, g_b, 0);

    fcgemm_kernel<<<dim3(4, 4, 32), 256>>>();
    fcsoftmax_kernel<<<dim3(256, 4), 256>>>();

    attn_kernel<<<dim3(32, 4), 256, 229376>>>();

    // y_c [n][d] = GN @ (f_c^T)^T
    wgemm<<<dim3(32, 2, 4), 256, 73728>>>(GN, IC, (size_t)NN*IC,
        FC, IC, (size_t)IC*IC, YC, IC, (size_t)NN*IC, IC, nullptr, 4);

    zmix_kernel<<<dim3(256, 4), 256>>>(x, Ws_w, Ws_b, Wc_w, Wc_b, gs, gc, out + 65536);
    conv1_kernel<<<dim3(4, 16, 4), dim3(32, 8)>>>(m1w, m1b);
    conv2_kernel<<<dim3(4, 16, 4), dim3(32, 8)>>>(m2w, m2b, out);
}

// round 10
// speedup vs baseline: 1.4518x; 1.4518x over previous
#include <cuda_runtime.h>
#include <cstdint>

#define BB 4
#define IC 256
#define NN 4096
#define HW 16384

// ---- scratch ----
__device__ __align__(16) float g_XT[BB*NN*IC];   // x^T   [b][n][c]
__device__ __align__(16) float g_TH[BB*NN*IC];   // theta [b][n][c]
__device__ __align__(16) float g_PH[BB*NN*IC];   // phi   [b][n][c]
__device__ __align__(16) float g_GX[BB*IC*NN];   // g     [b][o][n]
__device__ __align__(16) float g_GN[BB*NN*IC];   // g     [b][n][o]
__device__ __align__(16) float g_P [(size_t)BB*NN*NN]; // exp(S)
__device__ __align__(16) float g_Lp[BB*32*NN];
__device__ __align__(16) float g_Li[BB*NN];
__device__ __align__(16) float g_YS[BB*NN*IC];
__device__ __align__(16) float g_FCP[BB*8*IC*IC];
__device__ __align__(16) float g_FC[BB*IC*IC];   // f_c^T [b][d][c]
__device__ __align__(16) float g_YC[BB*NN*IC];
__device__ __align__(16) float g_Z [BB*64*HW];
__device__ __align__(16) float g_H [BB*16*HW];

static __device__ __forceinline__ uint32_t smem_u32(const void* p) {
    uint32_t a;
    asm("{ .reg .u64 t; cvta.to.shared.u64 t, %1; cvt.u32.u64 %0, t; }" : "=r"(a) : "l"(p));
    return a;
}
static __device__ __forceinline__ void mma8(float* d, const uint32_t* a, const uint32_t* b) {
    asm volatile(
        "mma.sync.aligned.m16n8k8.row.col.f32.tf32.tf32.f32 "
        "{%0,%1,%2,%3}, {%4,%5,%6,%7}, {%8,%9}, {%0,%1,%2,%3};"
        : "+f"(d[0]), "+f"(d[1]), "+f"(d[2]), "+f"(d[3])
        : "r"(a[0]), "r"(a[1]), "r"(a[2]), "r"(a[3]), "r"(b[0]), "r"(b[1]));
}
#define CPA(dst, src) asm volatile("cp.async.cg.shared.global [%0], [%1], 16;" :: "r"(dst), "l"(src))
#define CPC()  asm volatile("cp.async.commit_group;" ::: "memory")
#define CPW1() asm volatile("cp.async.wait_group 1;" ::: "memory")

// per-32K-chunk MMA on buffers uA [128][36], uB [128][36]
static __device__ __forceinline__ void chunk_mma(
    const uint32_t* __restrict__ uA, const uint32_t* __restrict__ uB,
    int wm, int wn, int gid, int tig, float (&acc)[2][8][4])
{
    #pragma unroll
    for (int ks = 0; ks < 4; ks++) {
        const int kk = ks*8;
        uint32_t af[2][4], bf[8][2];
        #pragma unroll
        for (int i = 0; i < 2; i++) {
            const int rb = wm*32 + i*16;
            af[i][0] = uA[(rb+gid)*36 + kk+tig];
            af[i][1] = uA[(rb+8+gid)*36 + kk+tig];
            af[i][2] = uA[(rb+gid)*36 + kk+tig+4];
            af[i][3] = uA[(rb+8+gid)*36 + kk+tig+4];
        }
        #pragma unroll
        for (int j = 0; j < 8; j++) {
            const int nb = wn*64 + j*8 + gid;
            bf[j][0] = uB[nb*36 + kk+tig];
            bf[j][1] = uB[nb*36 + kk+tig+4];
        }
        #pragma unroll
        for (int i = 0; i < 2; i++)
            #pragma unroll
            for (int j = 0; j < 8; j++)
                mma8(acc[i][j], af[i], bf[j]);
    }
}

// SMEM: A stages 0/18432/36864, B stages 55296+...; total 110592 B
#define STG 18432u
#define BOFF 55296u
#define SMSZ 110592

// ============================================================
// generic 3-stage wgemm: D = A @ B^T, 128x128 CTA tile
// mode 1: +aux[row]; 2: exp + row partsums->aux2; 3: *aux[b*NN+row]; else plain
// ============================================================
__global__ __launch_bounds__(256, 2) void wgemm(
    const float* __restrict__ A, int ldA, size_t Abs,
    const float* __restrict__ B, int ldB, size_t Bbs,
    float* __restrict__ D, int ldD, size_t Dbs,
    int K, const float* __restrict__ aux, float* __restrict__ aux2, int mode)
{
    extern __shared__ __align__(16) char wsm[];
    __shared__ float sred[2][128];
    const uint32_t sb = smem_u32(wsm);
    const uint32_t* uS = (const uint32_t*)wsm;
    const int tid = threadIdx.x, wid = tid >> 5, lane = tid & 31;
    const int gid = lane >> 2, tig = lane & 3;
    const int wm = wid & 3, wn = wid >> 2;
    const float* At = A + (size_t)blockIdx.z*Abs + (size_t)blockIdx.x*128*ldA;
    const float* Bt = B + (size_t)blockIdx.z*Bbs + (size_t)blockIdx.y*128*ldB;
    float acc[2][8][4] = {};
    const int NC = K >> 5;

    auto load_chunk = [&](int kc) {
        const uint32_t so = (uint32_t)(kc % 3)*STG;
        const int ko = kc*32;
        #pragma unroll
        for (int l = 0; l < 4; l++) {
            int f = l*256 + tid, r = f >> 3, c4 = (f & 7)*4;
            CPA(sb + so + (uint32_t)(r*36 + c4)*4, At + (size_t)r*ldA + ko + c4);
            CPA(sb + BOFF + so + (uint32_t)(r*36 + c4)*4, Bt + (size_t)r*ldB + ko + c4);
        }
    };
    load_chunk(0); CPC();
    load_chunk(1); CPC();

    #pragma unroll 1
    for (int kc = 0; kc < NC; kc++) {
        CPW1();
        __syncthreads();
        if (kc + 2 < NC) { load_chunk(kc + 2); CPC(); }
        const int st = kc % 3;
        chunk_mma(uS + st*4608, uS + 13824 + st*4608, wm, wn, gid, tig, acc);
    }

    float* Dt = D + (size_t)blockIdx.z*Dbs + (size_t)blockIdx.x*128*ldD + blockIdx.y*128;
    #pragma unroll
    for (int i = 0; i < 2; i++) {
        const int r0 = wm*32 + i*16 + gid, r1 = r0 + 8;
        float add0 = 0.f, add1 = 0.f, mul0 = 1.f, mul1 = 1.f;
        if (mode == 1) {
            add0 = aux[blockIdx.x*128 + r0];
            add1 = aux[blockIdx.x*128 + r1];
        } else if (mode == 3) {
            mul0 = aux[(size_t)blockIdx.z*NN + blockIdx.x*128 + r0];
            mul1 = aux[(size_t)blockIdx.z*NN + blockIdx.x*128 + r1];
        }
        float ls0 = 0.f, ls1 = 0.f;
        #pragma unroll
        for (int j = 0; j < 8; j++) {
            const int cl = wn*64 + j*8 + 2*tig;
            float v0 = acc[i][j][0], v1 = acc[i][j][1];
            float v2 = acc[i][j][2], v3 = acc[i][j][3];
            if (mode == 1) {
                v0 += add0; v1 += add0; v2 += add1; v3 += add1;
            } else if (mode == 2) {
                v0 = __expf(v0); v1 = __expf(v1);
                v2 = __expf(v2); v3 = __expf(v3);
                ls0 += v0 + v1; ls1 += v2 + v3;
            } else if (mode == 3) {
                v0 *= mul0; v1 *= mul0; v2 *= mul1; v3 *= mul1;
            }
            *(float2*)(Dt + (size_t)r0*ldD + cl) = make_float2(v0, v1);
            *(float2*)(Dt + (size_t)r1*ldD + cl) = make_float2(v2, v3);
        }
        if (mode == 2) {
            ls0 += __shfl_xor_sync(0xffffffffu, ls0, 1);
            ls0 += __shfl_xor_sync(0xffffffffu, ls0, 2);
            ls1 += __shfl_xor_sync(0xffffffffu, ls1, 1);
            ls1 += __shfl_xor_sync(0xffffffffu, ls1, 2);
            if (tig == 0) { sred[wn][r0] = ls0; sred[wn][r1] = ls1; }
        }
    }
    if (mode == 2) {
        __syncthreads();
        if (tid < 128)
            aux2[((size_t)blockIdx.z*gridDim.y + blockIdx.y)*NN + blockIdx.x*128 + tid]
                = sred[0][tid] + sred[1][tid];
    }
}

// ============================================================
// fused theta/phi/g_n projections: grid (32 ntiles, 6, 4)
// sel = by>>1 chooses weight/bias/dst; col-bias epilogue
// ============================================================
__global__ __launch_bounds__(256, 2) void proj_all(
    const float* __restrict__ th_w, const float* __restrict__ ph_w,
    const float* __restrict__ gw,
    const float* __restrict__ th_b, const float* __restrict__ ph_b,
    const float* __restrict__ gb)
{
    extern __shared__ __align__(16) char wsm[];
    const uint32_t sb = smem_u32(wsm);
    const uint32_t* uS = (const uint32_t*)wsm;
    const int tid = threadIdx.x, wid = tid >> 5, lane = tid & 31;
    const int gid = lane >> 2, tig = lane & 3;
    const int wm = wid & 3, wn = wid >> 2;
    const int b = blockIdx.z, sel = blockIdx.y >> 1, ot = blockIdx.y & 1;
    const float* W = (sel == 0) ? th_w : (sel == 1) ? ph_w : gw;
    const float* bias = (sel == 0) ? th_b : (sel == 1) ? ph_b : gb;
    float* dst = (sel == 0) ? g_TH : (sel == 1) ? g_PH : g_GN;
    const float* At = g_XT + (size_t)b*NN*IC + (size_t)blockIdx.x*128*IC;
    const float* Bt = W + (size_t)ot*128*IC;
    float acc[2][8][4] = {};

    auto load_chunk = [&](int kc) {
        const uint32_t so = (uint32_t)(kc % 3)*STG;
        const int ko = kc*32;
        #pragma unroll
        for (int l = 0; l < 4; l++) {
            int f = l*256 + tid, r = f >> 3, c4 = (f & 7)*4;
            CPA(sb + so + (uint32_t)(r*36 + c4)*4, At + (size_t)r*IC + ko + c4);
            CPA(sb + BOFF + so + (uint32_t)(r*36 + c4)*4, Bt + (size_t)r*IC + ko + c4);
        }
    };
    load_chunk(0); CPC();
    load_chunk(1); CPC();
    #pragma unroll 1
    for (int kc = 0; kc < 8; kc++) {
        CPW1();
        __syncthreads();
        if (kc + 2 < 8) { load_chunk(kc + 2); CPC(); }
        const int st = kc % 3;
        chunk_mma(uS + st*4608, uS + 13824 + st*4608, wm, wn, gid, tig, acc);
    }
    float* Dt = dst + (size_t)b*NN*IC + (size_t)blockIdx.x*128*IC + ot*128;
    #pragma unroll
    for (int i = 0; i < 2; i++) {
        const int r0 = wm*32 + i*16 + gid, r1 = r0 + 8;
        #pragma unroll
        for (int j = 0; j < 8; j++) {
            const int cl = wn*64 + j*8 + 2*tig;
            float a0 = __ldg(&bias[ot*128 + cl]), a1 = __ldg(&bias[ot*128 + cl + 1]);
            *(float2*)(Dt + (size_t)r0*IC + cl) =
                make_float2(acc[i][j][0] + a0, acc[i][j][1] + a1);
            *(float2*)(Dt + (size_t)r1*IC + cl) =
                make_float2(acc[i][j][2] + a0, acc[i][j][3] + a1);
        }
    }
}

// x[b][c][n] -> g_XT[b][n][c]
__global__ __launch_bounds__(256) void transpose_kernel(const float* __restrict__ x)
{
    __shared__ float t[32][33];
    const int b = blockIdx.z, n0 = blockIdx.x*32, c0 = blockIdx.y*32;
    const int tx = threadIdx.x, ty = threadIdx.y;
    #pragma unroll
    for (int i = 0; i < 4; i++)
        t[ty + i*8][tx] = x[(size_t)b*IC*NN + (size_t)(c0 + ty + i*8)*NN + n0 + tx];
    __syncthreads();
    #pragma unroll
    for (int i = 0; i < 4; i++)
        g_XT[(size_t)b*NN*IC + (size_t)(n0 + ty + i*8)*IC + c0 + tx] = t[tx][ty + i*8];
}

// g_Li = 1/rowsum; grid (16,4)
__global__ __launch_bounds__(256) void lreduce_kernel()
{
    const int b = blockIdx.y, n = blockIdx.x*256 + threadIdx.x;
    float s = 0.f;
    #pragma unroll
    for (int mt = 0; mt < 32; mt++) s += g_Lp[((size_t)b*32 + mt)*NN + n];
    g_Li[(size_t)b*NN + n] = 1.0f / s;
}

// f_c partials, split-K x8: grid (4,4,32)
__global__ __launch_bounds__(256) void fcgemm_kernel()
{
    __shared__ __align__(16) float sA[32][68], sB[32][68];
    const int c0 = blockIdx.x*64, d0 = blockIdx.y*64;
    const int bz = blockIdx.z, b = bz >> 3, ks = bz & 7;
    const int tid = threadIdx.x, tx = tid & 15, ty = tid >> 4;
    const float* TH = g_TH + (size_t)b*NN*IC + (size_t)ks*512*IC;
    const float* PH = g_PH + (size_t)b*NN*IC + (size_t)ks*512*IC;
    float acc[4][4] = {};
    for (int n0 = 0; n0 < 512; n0 += 32) {
        #pragma unroll
        for (int l = 0; l < 8; l++) {
            int idx = l*256 + tid, ki = idx >> 6, ci = idx & 63;
            sA[ki][ci] = TH[(size_t)(n0 + ki)*IC + c0 + ci];
            sB[ki][ci] = PH[(size_t)(n0 + ki)*IC + d0 + ci];
        }
        __syncthreads();
        #pragma unroll
        for (int k = 0; k < 32; k++) {
            float a[4];
            #pragma unroll
            for (int i = 0; i < 4; i++) a[i] = sA[k][4*ty + i];
            float4 bv = *(const float4*)&sB[k][4*tx];
            float bb[4] = {bv.x, bv.y, bv.z, bv.w};
            #pragma unroll
            for (int i = 0; i < 4; i++)
                #pragma unroll
                for (int j = 0; j < 4; j++) acc[i][j] += a[i]*bb[j];
        }
        __syncthreads();
    }
    float* FCP = g_FCP + (size_t)bz*IC*IC;
    #pragma unroll
    for (int i = 0; i < 4; i++)
        #pragma unroll
        for (int j = 0; j < 4; j++)
            FCP[(c0 + 4*ty + i)*IC + d0 + 4*tx + j] = acc[i][j];
}

// reduce split-K + softmax over d; writes f_c^T[d][c]; grid (256,4)
__global__ __launch_bounds__(256) void fcsoftmax_kernel()
{
    __shared__ float red[256];
    const int b = blockIdx.y, c = blockIdx.x, tid = threadIdx.x;
    float v = 0.f;
    #pragma unroll
    for (int ks = 0; ks < 8; ks++)
        v += g_FCP[(((size_t)b*8 + ks)*IC + c)*IC + tid];
    red[tid] = v; __syncthreads();
    for (int s = 128; s > 0; s >>= 1) {
        if (tid < s) red[tid] = fmaxf(red[tid], red[tid + s]);
        __syncthreads();
    }
    float m = red[0]; __syncthreads();
    float e = __expf(v - m);
    red[tid] = e; __syncthreads();
    for (int s = 128; s > 0; s >>= 1) {
        if (tid < s) red[tid] += red[tid + s];
        __syncthreads();
    }
    g_FC[(size_t)b*IC*IC + (size_t)tid*IC + c] = e / red[0];
}

// z = x + gs*(Ws@ys+b) + gc*(Wc@yc+b); grid (256,4)
__global__ __launch_bounds__(256) void zmix_kernel(
    const float* __restrict__ x,
    const float* __restrict__ Ws_w, const float* __restrict__ Ws_b,
    const float* __restrict__ Wc_w, const float* __restrict__ Wc_b,
    const float* __restrict__ gs, const float* __restrict__ gc,
    float* __restrict__ zout)
{
    __shared__ float sW[64][64];
    __shared__ float sD[64][65];
    const int b = blockIdx.y, p0 = blockIdx.x*64;
    const int tid = threadIdx.x, tx = tid & 63, ty = tid >> 6;
    float accs[16] = {}, accc[16] = {};
    #pragma unroll
    for (int l = 0; l < 16; l++) {
        int idx = l*256 + tid;
        sW[idx >> 6][idx & 63] = Ws_w[idx];
        int i = idx >> 6, px = idx & 63;
        int p = p0 + px, h = p >> 7, w = p & 127;
        int o = 4*i + (h >> 5), n = ((h & 31) << 7) | w;
        sD[i][px] = g_YS[((size_t)(b << 12) + n)*IC + o];
    }
    __syncthreads();
    #pragma unroll 4
    for (int i = 0; i < 64; i++) {
        float yv = sD[i][tx];
        #pragma unroll
        for (int k = 0; k < 16; k++) accs[k] += sW[16*ty + k][i]*yv;
    }
    __syncthreads();
    #pragma unroll
    for (int l = 0; l < 16; l++) {
        int idx = l*256 + tid;
        sW[idx >> 6][idx & 63] = Wc_w[idx];
        int i = idx >> 6, px = idx & 63;
        int p = p0 + px, h = p >> 7, w = p & 127;
        int n = (i << 6) + (h >> 1), d = ((h & 1) << 7) | w;
        sD[i][px] = g_YC[((size_t)(b << 12) + n)*IC + d];
    }
    __syncthreads();
    #pragma unroll 4
    for (int i = 0; i < 64; i++) {
        float cv = sD[i][tx];
        #pragma unroll
        for (int k = 0; k < 16; k++) accc[k] += sW[16*ty + k][i]*cv;
    }
    float gsv = gs[0], gcv = gc[0];
    int p = p0 + tx;
    #pragma unroll
    for (int k = 0; k < 16; k++) {
        int oc = 16*ty + k;
        size_t idx = (size_t)(b*64 + oc)*HW + p;
        float z = x[idx] + gsv*(accs[k] + Ws_b[oc]) + gcv*(accc[k] + Wc_b[oc]);
        g_Z[idx] = z;
        zout[idx] = z;
    }
}

// conv3x3 64->16 + relu; grid (4,16,4), block (32,8)
__global__ __launch_bounds__(256) void conv1_kernel(
    const float* __restrict__ m1w, const float* __restrict__ m1b)
{
    __shared__ float sw[16*64*9];
    __shared__ float st[10][36];
    const int b = blockIdx.z, h0 = blockIdx.y*8, w0 = blockIdx.x*32;
    const int tx = threadIdx.x, ty = threadIdx.y, tid = ty*32 + tx;
    for (int i = tid; i < 9216; i += 256) sw[i] = m1w[i];
    float acc[16];
    #pragma unroll
    for (int oc = 0; oc < 16; oc++) acc[oc] = m1b[oc];
    for (int ic = 0; ic < 64; ic++) {
        const float* zp = g_Z + (size_t)(b*64 + ic)*HW;
        __syncthreads();
        for (int l = tid; l < 340; l += 256) {
            int yy = l / 34, xx = l % 34;
            int hh = h0 - 1 + yy, ww = w0 - 1 + xx;
            st[yy][xx] = (hh >= 0 && hh < 128 && ww >= 0 && ww < 128) ? zp[hh*128 + ww] : 0.f;
        }
        __syncthreads();
        #pragma unroll
        for (int dy = 0; dy < 3; dy++)
            #pragma unroll
            for (int dx = 0; dx < 3; dx++) {
                float zv = st[ty + dy][tx + dx];
                #pragma unroll
                for (int oc = 0; oc < 16; oc++)
                    acc[oc] += sw[(oc*64 + ic)*9 + dy*3 + dx]*zv;
            }
    }
    int h = h0 + ty, w = w0 + tx;
    #pragma unroll
    for (int oc = 0; oc < 16; oc++)
        g_H[(size_t)(b*16 + oc)*HW + h*128 + w] = fmaxf(acc[oc], 0.f);
}

// conv3x3 16->1; grid (4,16,4), block (32,8)
__global__ __launch_bounds__(256) void conv2_kernel(
    const float* __restrict__ m2w, const float* __restrict__ m2b,
    float* __restrict__ out)
{
    __shared__ float sw[144];
    __shared__ float st[10][36];
    const int b = blockIdx.z, h0 = blockIdx.y*8, w0 = blockIdx.x*32;
    const int tx = threadIdx.x, ty = threadIdx.y, tid = ty*32 + tx;
    if (tid < 144) sw[tid] = m2w[tid];
    float acc = m2b[0];
    for (int ic = 0; ic < 16; ic++) {
        const float* hp = g_H + (size_t)(b*16 + ic)*HW;
        __syncthreads();
        for (int l = tid; l < 340; l += 256) {
            int yy = l / 34, xx = l % 34;
            int hh = h0 - 1 + yy, ww = w0 - 1 + xx;
            st[yy][xx] = (hh >= 0 && hh < 128 && ww >= 0 && ww < 128) ? hp[hh*128 + ww] : 0.f;
        }
        __syncthreads();
        #pragma unroll
        for (int dy = 0; dy < 3; dy++)
            #pragma unroll
            for (int dx = 0; dx < 3; dx++)
                acc += sw[ic*9 + dy*3 + dx]*st[ty + dy][tx + dx];
    }
    out[(size_t)b*HW + (h0 + ty)*128 + (w0 + tx)] = acc;
}

extern "C" void kernel_launch(void* const* d_in, const int* in_sizes, int n_in,
                              void* d_out, int out_size)
{
    const float* x    = (const float*)d_in[0];
    const float* g_w  = (const float*)d_in[1];
    const float* g_b  = (const float*)d_in[2];
    const float* th_w = (const float*)d_in[3];
    const float* th_b = (const float*)d_in[4];
    const float* ph_w = (const float*)d_in[5];
    const float* ph_b = (const float*)d_in[6];
    const float* Ws_w = (const float*)d_in[7];
    const float* Ws_b = (const float*)d_in[8];
    const float* Wc_w = (const float*)d_in[9];
    const float* Wc_b = (const float*)d_in[10];
    const float* gs   = (const float*)d_in[11];
    const float* gc   = (const float*)d_in[12];
    const float* m1w  = (const float*)d_in[13];
    const float* m1b  = (const float*)d_in[14];
    const float* m2w  = (const float*)d_in[15];
    const float* m2b  = (const float*)d_in[16];
    float* out = (float*)d_out;   // logit [4*16384] then z [4*64*16384]

    cudaFuncSetAttribute(wgemm, cudaFuncAttributeMaxDynamicSharedMemorySize, SMSZ);
    cudaFuncSetAttribute(proj_all, cudaFuncAttributeMaxDynamicSharedMemorySize, SMSZ);

    float *XT, *TH, *PH, *GX, *GN, *P, *Lp, *Li, *YS, *FC, *YC;
    cudaGetSymbolAddress((void**)&XT, g_XT);
    cudaGetSymbolAddress((void**)&TH, g_TH);
    cudaGetSymbolAddress((void**)&PH, g_PH);
    cudaGetSymbolAddress((void**)&GX, g_GX);
    cudaGetSymbolAddress((void**)&GN, g_GN);
    cudaGetSymbolAddress((void**)&P,  g_P);
    cudaGetSymbolAddress((void**)&Lp, g_Lp);
    cudaGetSymbolAddress((void**)&Li, g_Li);
    cudaGetSymbolAddress((void**)&YS, g_YS);
    cudaGetSymbolAddress((void**)&FC, g_FC);
    cudaGetSymbolAddress((void**)&YC, g_YC);

    transpose_kernel<<<dim3(128, 8, 4), dim3(32, 8)>>>(x);

    // theta/phi/g_n [n][c] in one launch
    proj_all<<<dim3(32, 6, 4), 256, SMSZ>>>(th_w, ph_w, g_w, th_b, ph_b, g_b);
    // g [o][n] = g_w @ XT^T + bias(row)
    wgemm<<<dim3(2, 32, 4), 256, SMSZ>>>(g_w, IC, 0,
        XT, IC, (size_t)NN*IC, GX, NN, (size_t)IC*NN, IC, g_b, nullptr, 1);

    fcgemm_kernel<<<dim3(4, 4, 32), 256>>>();
    fcsoftmax_kernel<<<dim3(256, 4), 256>>>();

    // P = exp(TH @ PH^T), fused row partial sums
    wgemm<<<dim3(32, 32, 4), 256, SMSZ>>>(TH, IC, (size_t)NN*IC,
        PH, IC, (size_t)NN*IC, P, NN, (size_t)NN*NN, IC, nullptr, Lp, 2);
    lreduce_kernel<<<dim3(16, 4), 256>>>();
    // y_s = (P @ GX^T) * Li[row]
    wgemm<<<dim3(32, 2, 4), 256, SMSZ>>>(P, NN, (size_t)NN*NN,
        GX, NN, (size_t)IC*NN, YS, IC, (size_t)NN*IC, NN, Li, nullptr, 3);
    // y_c = GN @ (f_c^T)^T
    wgemm<<<dim3(32, 2, 4), 256, SMSZ>>>(GN, IC, (size_t)NN*IC,
        FC, IC, (size_t)IC*IC, YC, IC, (size_t)NN*IC, IC, nullptr, nullptr, 4);

    zmix_kernel<<<dim3(256, 4), 256>>>(x, Ws_w, Ws_b, Wc_w, Wc_b, gs, gc, out + 65536);
    conv1_kernel<<<dim3(4, 16, 4), dim3(32, 8)>>>(m1w, m1b);
    conv2_kernel<<<dim3(4, 16, 4), dim3(32, 8)>>>(m2w, m2b, out);
}

// round 11
// speedup vs baseline: 1.5619x; 1.0759x over previous
#include <cuda_runtime.h>
#include <cstdint>

#define BB 4
#define IC 256
#define NN 4096
#define HW 16384

// ---- scratch ----
__device__ __align__(16) float g_XT[BB*NN*IC];   // x^T   [b][n][c]
__device__ __align__(16) float g_TH[BB*NN*IC];   // theta [b][n][c]
__device__ __align__(16) float g_PH[BB*NN*IC];   // phi   [b][n][c]
__device__ __align__(16) float g_GX[BB*IC*NN];   // g     [b][o][n]
__device__ __align__(16) float g_GN[BB*NN*IC];   // g     [b][n][o]
__device__ __align__(16) float g_P [(size_t)BB*NN*NN]; // exp(S)
__device__ __align__(16) float g_Lp[BB*32*NN];
__device__ __align__(16) float g_Li[BB*NN];
__device__ __align__(16) float g_YS[BB*NN*IC];
__device__ __align__(16) float g_FCP[BB*16*IC*IC];
__device__ __align__(16) float g_FC[BB*IC*IC];   // f_c^T [b][d][c]
__device__ __align__(16) float g_YC[BB*NN*IC];
__device__ __align__(16) float g_Z [BB*64*HW];
__device__ __align__(16) float g_H [BB*16*HW];

static __device__ __forceinline__ uint32_t smem_u32(const void* p) {
    uint32_t a;
    asm("{ .reg .u64 t; cvta.to.shared.u64 t, %1; cvt.u32.u64 %0, t; }" : "=r"(a) : "l"(p));
    return a;
}
static __device__ __forceinline__ void mma8(float* d, const uint32_t* a, const uint32_t* b) {
    asm volatile(
        "mma.sync.aligned.m16n8k8.row.col.f32.tf32.tf32.f32 "
        "{%0,%1,%2,%3}, {%4,%5,%6,%7}, {%8,%9}, {%0,%1,%2,%3};"
        : "+f"(d[0]), "+f"(d[1]), "+f"(d[2]), "+f"(d[3])
        : "r"(a[0]), "r"(a[1]), "r"(a[2]), "r"(a[3]), "r"(b[0]), "r"(b[1]));
}
#define CPA(dst, src) asm volatile("cp.async.cg.shared.global [%0], [%1], 16;" :: "r"(dst), "l"(src))
#define CPC()  asm volatile("cp.async.commit_group;" ::: "memory")
#define CPW1() asm volatile("cp.async.wait_group 1;" ::: "memory")

// SMEM: A stages 0/18432/36864, B stages 55296+...; total 110592 B
#define STG 18432u
#define BOFF 55296u
#define SMSZ 110592

// ============================================================
// wgemm: 128 threads, 4 warps of 64x64, CTA tile 128x128, 3-stage cp.async
// D = A @ B^T; A [M][K] ldA, B [N][K] ldB, K%32==0
// mode 0: +aux[col]; 1: +aux[row]; 2: exp + row partsums->aux2;
// 3: *aux[b*NN+row]; else plain
// ============================================================
__global__ __launch_bounds__(128, 2) void wgemm(
    const float* __restrict__ A, int ldA, size_t Abs,
    const float* __restrict__ B, int ldB, size_t Bbs,
    float* __restrict__ D, int ldD, size_t Dbs,
    int K, const float* __restrict__ aux, float* __restrict__ aux2, int mode)
{
    extern __shared__ __align__(16) char wsm[];
    __shared__ float sred[2][128];
    const uint32_t sb = smem_u32(wsm);
    const uint32_t* uS = (const uint32_t*)wsm;
    const int tid = threadIdx.x, wid = tid >> 5, lane = tid & 31;
    const int gid = lane >> 2, tig = lane & 3;
    const int wm = wid & 1, wn = wid >> 1;           // 2x2 warps, 64x64 each
    const float* At = A + (size_t)blockIdx.z*Abs + (size_t)blockIdx.x*128*ldA;
    const float* Bt = B + (size_t)blockIdx.z*Bbs + (size_t)blockIdx.y*128*ldB;
    float acc[4][8][4] = {};
    const int NC = K >> 5;

    auto load_chunk = [&](int kc) {
        const uint32_t so = (uint32_t)(kc % 3)*STG;
        const int ko = kc*32;
        #pragma unroll
        for (int l = 0; l < 8; l++) {
            int f = l*128 + tid, r = f >> 3, c4 = (f & 7)*4;
            CPA(sb + so + (uint32_t)(r*36 + c4)*4, At + (size_t)r*ldA + ko + c4);
            CPA(sb + BOFF + so + (uint32_t)(r*36 + c4)*4, Bt + (size_t)r*ldB + ko + c4);
        }
    };
    load_chunk(0); CPC();
    load_chunk(1); CPC();

    #pragma unroll 1
    for (int kc = 0; kc < NC; kc++) {
        CPW1();
        __syncthreads();
        if (kc + 2 < NC) { load_chunk(kc + 2); CPC(); }
        const int st = kc % 3;
        const uint32_t* uA = uS + st*4608;
        const uint32_t* uB = uS + 13824 + st*4608;
        #pragma unroll
        for (int ks = 0; ks < 4; ks++) {
            const int kk = ks*8;
            uint32_t af[4][4], bf[8][2];
            #pragma unroll
            for (int i = 0; i < 4; i++) {
                const int rb = wm*64 + i*16;
                af[i][0] = uA[(rb+gid)*36 + kk+tig];
                af[i][1] = uA[(rb+8+gid)*36 + kk+tig];
                af[i][2] = uA[(rb+gid)*36 + kk+tig+4];
                af[i][3] = uA[(rb+8+gid)*36 + kk+tig+4];
            }
            #pragma unroll
            for (int j = 0; j < 8; j++) {
                const int nb = wn*64 + j*8 + gid;
                bf[j][0] = uB[nb*36 + kk+tig];
                bf[j][1] = uB[nb*36 + kk+tig+4];
            }
            #pragma unroll
            for (int i = 0; i < 4; i++)
                #pragma unroll
                for (int j = 0; j < 8; j++)
                    mma8(acc[i][j], af[i], bf[j]);
        }
    }

    float* Dt = D + (size_t)blockIdx.z*Dbs + (size_t)blockIdx.x*128*ldD + blockIdx.y*128;
    #pragma unroll
    for (int i = 0; i < 4; i++) {
        const int r0 = wm*64 + i*16 + gid, r1 = r0 + 8;
        float add0 = 0.f, add1 = 0.f, mul0 = 1.f, mul1 = 1.f;
        if (mode == 1) {
            add0 = aux[blockIdx.x*128 + r0];
            add1 = aux[blockIdx.x*128 + r1];
        } else if (mode == 3) {
            mul0 = aux[(size_t)blockIdx.z*NN + blockIdx.x*128 + r0];
            mul1 = aux[(size_t)blockIdx.z*NN + blockIdx.x*128 + r1];
        }
        float ls0 = 0.f, ls1 = 0.f;
        #pragma unroll
        for (int j = 0; j < 8; j++) {
            const int cl = wn*64 + j*8 + 2*tig;
            float v0 = acc[i][j][0], v1 = acc[i][j][1];
            float v2 = acc[i][j][2], v3 = acc[i][j][3];
            if (mode == 0) {
                const int cg = blockIdx.y*128 + cl;
                float a0 = __ldg(&aux[cg]), a1 = __ldg(&aux[cg+1]);
                v0 += a0; v1 += a1; v2 += a0; v3 += a1;
            } else if (mode == 1) {
                v0 += add0; v1 += add0; v2 += add1; v3 += add1;
            } else if (mode == 2) {
                v0 = __expf(v0); v1 = __expf(v1);
                v2 = __expf(v2); v3 = __expf(v3);
                ls0 += v0 + v1; ls1 += v2 + v3;
            } else if (mode == 3) {
                v0 *= mul0; v1 *= mul0; v2 *= mul1; v3 *= mul1;
            }
            *(float2*)(Dt + (size_t)r0*ldD + cl) = make_float2(v0, v1);
            *(float2*)(Dt + (size_t)r1*ldD + cl) = make_float2(v2, v3);
        }
        if (mode == 2) {
            ls0 += __shfl_xor_sync(0xffffffffu, ls0, 1);
            ls0 += __shfl_xor_sync(0xffffffffu, ls0, 2);
            ls1 += __shfl_xor_sync(0xffffffffu, ls1, 1);
            ls1 += __shfl_xor_sync(0xffffffffu, ls1, 2);
            if (tig == 0) { sred[wn][r0] = ls0; sred[wn][r1] = ls1; }
        }
    }
    if (mode == 2) {
        __syncthreads();
        if (tid < 128)
            aux2[((size_t)blockIdx.z*gridDim.y + blockIdx.y)*NN + blockIdx.x*128 + tid]
                = sred[0][tid] + sred[1][tid];
    }
}

// ============================================================
// TN tensor GEMM for f_c: D[c][d] partial = sum_n TH[n][c]*PH[n][d]
// tiles stored [32 k][136 c] (conflict-free transposed fragments)
// grid (2, 2, 64 = b*16+ks), 128 threads; split-K x16 (256 rows each)
// ============================================================
#define TSTG 17408u
#define TBOFF 52224u
#define TSMSZ 104448

__global__ __launch_bounds__(128, 2) void fcgemm_tn()
{
    extern __shared__ __align__(16) char wsm[];
    const uint32_t sb = smem_u32(wsm);
    const uint32_t* uS = (const uint32_t*)wsm;
    const int tid = threadIdx.x, wid = tid >> 5, lane = tid & 31;
    const int gid = lane >> 2, tig = lane & 3;
    const int wm = wid & 1, wn = wid >> 1;
    const int bz = blockIdx.z, b = bz >> 4, ks = bz & 15;
    const float* At = g_TH + ((size_t)b*NN + ks*256)*IC + blockIdx.x*128;
    const float* Bt = g_PH + ((size_t)b*NN + ks*256)*IC + blockIdx.y*128;
    float acc[4][8][4] = {};

    auto load_chunk = [&](int kc) {
        const uint32_t so = (uint32_t)(kc % 3)*TSTG;
        const size_t ro = (size_t)(kc*32)*IC;
        #pragma unroll
        for (int l = 0; l < 8; l++) {
            int f = l*128 + tid, kr = f >> 5, c4 = (f & 31)*4;
            CPA(sb + so + (uint32_t)(kr*136 + c4)*4, At + ro + (size_t)kr*IC + c4);
            CPA(sb + TBOFF + so + (uint32_t)(kr*136 + c4)*4, Bt + ro + (size_t)kr*IC + c4);
        }
    };
    load_chunk(0); CPC();
    load_chunk(1); CPC();

    #pragma unroll 1
    for (int kc = 0; kc < 8; kc++) {
        CPW1();
        __syncthreads();
        if (kc + 2 < 8) { load_chunk(kc + 2); CPC(); }
        const int st = kc % 3;
        const uint32_t* uA = uS + st*4352;
        const uint32_t* uB = uS + 13056 + st*4352;
        #pragma unroll
        for (int ksl = 0; ksl < 4; ksl++) {
            const int kk = ksl*8;
            uint32_t af[4][4], bf[8][2];
            #pragma unroll
            for (int i = 0; i < 4; i++) {
                const int rb = wm*64 + i*16;
                af[i][0] = uA[(kk+tig)*136 + rb+gid];
                af[i][1] = uA[(kk+tig)*136 + rb+8+gid];
                af[i][2] = uA[(kk+tig+4)*136 + rb+gid];
                af[i][3] = uA[(kk+tig+4)*136 + rb+8+gid];
            }
            #pragma unroll
            for (int j = 0; j < 8; j++) {
                const int nb = wn*64 + j*8 + gid;
                bf[j][0] = uB[(kk+tig)*136 + nb];
                bf[j][1] = uB[(kk+tig+4)*136 + nb];
            }
            #pragma unroll
            for (int i = 0; i < 4; i++)
                #pragma unroll
                for (int j = 0; j < 8; j++)
                    mma8(acc[i][j], af[i], bf[j]);
        }
    }
    float* Dt = g_FCP + ((size_t)bz*IC + blockIdx.x*128)*IC + blockIdx.y*128;
    #pragma unroll
    for (int i = 0; i < 4; i++) {
        const int r0 = wm*64 + i*16 + gid, r1 = r0 + 8;
        #pragma unroll
        for (int j = 0; j < 8; j++) {
            const int cl = wn*64 + j*8 + 2*tig;
            *(float2*)(Dt + (size_t)r0*IC + cl) = make_float2(acc[i][j][0], acc[i][j][1]);
            *(float2*)(Dt + (size_t)r1*IC + cl) = make_float2(acc[i][j][2], acc[i][j][3]);
        }
    }
}

// x[b][c][n] -> g_XT[b][n][c]
__global__ __launch_bounds__(256) void transpose_kernel(const float* __restrict__ x)
{
    __shared__ float t[32][33];
    const int b = blockIdx.z, n0 = blockIdx.x*32, c0 = blockIdx.y*32;
    const int tx = threadIdx.x, ty = threadIdx.y;
    #pragma unroll
    for (int i = 0; i < 4; i++)
        t[ty + i*8][tx] = x[(size_t)b*IC*NN + (size_t)(c0 + ty + i*8)*NN + n0 + tx];
    __syncthreads();
    #pragma unroll
    for (int i = 0; i < 4; i++)
        g_XT[(size_t)b*NN*IC + (size_t)(n0 + ty + i*8)*IC + c0 + tx] = t[tx][ty + i*8];
}

// g_Li = 1/rowsum; grid (16,4)
__global__ __launch_bounds__(256) void lreduce_kernel()
{
    const int b = blockIdx.y, n = blockIdx.x*256 + threadIdx.x;
    float s = 0.f;
    #pragma unroll
    for (int mt = 0; mt < 32; mt++) s += g_Lp[((size_t)b*32 + mt)*NN + n];
    g_Li[(size_t)b*NN + n] = 1.0f / s;
}

// reduce split-K x16 + softmax over d; writes f_c^T[d][c]; grid (256,4)
__global__ __launch_bounds__(256) void fcsoftmax_kernel()
{
    __shared__ float red[256];
    const int b = blockIdx.y, c = blockIdx.x, tid = threadIdx.x;
    float v = 0.f;
    #pragma unroll
    for (int ks = 0; ks < 16; ks++)
        v += g_FCP[(((size_t)b*16 + ks)*IC + c)*IC + tid];
    red[tid] = v; __syncthreads();
    for (int s = 128; s > 0; s >>= 1) {
        if (tid < s) red[tid] = fmaxf(red[tid], red[tid + s]);
        __syncthreads();
    }
    float m = red[0]; __syncthreads();
    float e = __expf(v - m);
    red[tid] = e; __syncthreads();
    for (int s = 128; s > 0; s >>= 1) {
        if (tid < s) red[tid] += red[tid + s];
        __syncthreads();
    }
    g_FC[(size_t)b*IC*IC + (size_t)tid*IC + c] = e / red[0];
}

// z = x + gs*(Ws@ys+b) + gc*(Wc@yc+b); grid (256,4)
__global__ __launch_bounds__(256) void zmix_kernel(
    const float* __restrict__ x,
    const float* __restrict__ Ws_w, const float* __restrict__ Ws_b,
    const float* __restrict__ Wc_w, const float* __restrict__ Wc_b,
    const float* __restrict__ gs, const float* __restrict__ gc,
    float* __restrict__ zout)
{
    __shared__ float sW[64][64];
    __shared__ float sD[64][65];
    const int b = blockIdx.y, p0 = blockIdx.x*64;
    const int tid = threadIdx.x, tx = tid & 63, ty = tid >> 6;
    float accs[16] = {}, accc[16] = {};
    #pragma unroll
    for (int l = 0; l < 16; l++) {
        int idx = l*256 + tid;
        sW[idx >> 6][idx & 63] = Ws_w[idx];
        int i = idx >> 6, px = idx & 63;
        int p = p0 + px, h = p >> 7, w = p & 127;
        int o = 4*i + (h >> 5), n = ((h & 31) << 7) | w;
        sD[i][px] = g_YS[((size_t)(b << 12) + n)*IC + o];
    }
    __syncthreads();
    #pragma unroll 4
    for (int i = 0; i < 64; i++) {
        float yv = sD[i][tx];
        #pragma unroll
        for (int k = 0; k < 16; k++) accs[k] += sW[16*ty + k][i]*yv;
    }
    __syncthreads();
    #pragma unroll
    for (int l = 0; l < 16; l++) {
        int idx = l*256 + tid;
        sW[idx >> 6][idx & 63] = Wc_w[idx];
        int i = idx >> 6, px = idx & 63;
        int p = p0 + px, h = p >> 7, w = p & 127;
        int n = (i << 6) + (h >> 1), d = ((h & 1) << 7) | w;
        sD[i][px] = g_YC[((size_t)(b << 12) + n)*IC + d];
    }
    __syncthreads();
    #pragma unroll 4
    for (int i = 0; i < 64; i++) {
        float cv = sD[i][tx];
        #pragma unroll
        for (int k = 0; k < 16; k++) accc[k] += sW[16*ty + k][i]*cv;
    }
    float gsv = gs[0], gcv = gc[0];
    int p = p0 + tx;
    #pragma unroll
    for (int k = 0; k < 16; k++) {
        int oc = 16*ty + k;
        size_t idx = (size_t)(b*64 + oc)*HW + p;
        float z = x[idx] + gsv*(accs[k] + Ws_b[oc]) + gcv*(accc[k] + Wc_b[oc]);
        g_Z[idx] = z;
        zout[idx] = z;
    }
}

// conv3x3 64->16 + relu, double-buffered halo; grid (4,16,4), block (32,8)
__global__ __launch_bounds__(256) void conv1_kernel(
    const float* __restrict__ m1w, const float* __restrict__ m1b)
{
    __shared__ float sw[16*64*9];
    __shared__ float st[2][10][36];
    const int b = blockIdx.z, h0 = blockIdx.y*8, w0 = blockIdx.x*32;
    const int tx = threadIdx.x, ty = threadIdx.y, tid = ty*32 + tx;
    for (int i = tid; i < 9216; i += 256) sw[i] = m1w[i];
    float acc[16];
    #pragma unroll
    for (int oc = 0; oc < 16; oc++) acc[oc] = m1b[oc];

    auto load_tile = [&](int ic, int buf) {
        const float* zp = g_Z + (size_t)(b*64 + ic)*HW;
        for (int l = tid; l < 340; l += 256) {
            int yy = l / 34, xx = l % 34;
            int hh = h0 - 1 + yy, ww = w0 - 1 + xx;
            st[buf][yy][xx] = (hh >= 0 && hh < 128 && ww >= 0 && ww < 128)
                              ? zp[hh*128 + ww] : 0.f;
        }
    };
    load_tile(0, 0);
    __syncthreads();
    for (int ic = 0; ic < 64; ic++) {
        if (ic + 1 < 64) load_tile(ic + 1, (ic + 1) & 1);
        const int cb = ic & 1;
        #pragma unroll
        for (int dy = 0; dy < 3; dy++)
            #pragma unroll
            for (int dx = 0; dx < 3; dx++) {
                float zv = st[cb][ty + dy][tx + dx];
                #pragma unroll
                for (int oc = 0; oc < 16; oc++)
                    acc[oc] += sw[(oc*64 + ic)*9 + dy*3 + dx]*zv;
            }
        __syncthreads();
    }
    int h = h0 + ty, w = w0 + tx;
    #pragma unroll
    for (int oc = 0; oc < 16; oc++)
        g_H[(size_t)(b*16 + oc)*HW + h*128 + w] = fmaxf(acc[oc], 0.f);
}

// conv3x3 16->1, double-buffered; grid (4,16,4), block (32,8)
__global__ __launch_bounds__(256) void conv2_kernel(
    const float* __restrict__ m2w, const float* __restrict__ m2b,
    float* __restrict__ out)
{
    __shared__ float sw[144];
    __shared__ float st[2][10][36];
    const int b = blockIdx.z, h0 = blockIdx.y*8, w0 = blockIdx.x*32;
    const int tx = threadIdx.x, ty = threadIdx.y, tid = ty*32 + tx;
    if (tid < 144) sw[tid] = m2w[tid];
    float acc = m2b[0];
    auto load_tile = [&](int ic, int buf) {
        const float* hp = g_H + (size_t)(b*16 + ic)*HW;
        for (int l = tid; l < 340; l += 256) {
            int yy = l / 34, xx = l % 34;
            int hh = h0 - 1 + yy, ww = w0 - 1 + xx;
            st[buf][yy][xx] = (hh >= 0 && hh < 128 && ww >= 0 && ww < 128)
                              ? hp[hh*128 + ww] : 0.f;
        }
    };
    load_tile(0, 0);
    __syncthreads();
    for (int ic = 0; ic < 16; ic++) {
        if (ic + 1 < 16) load_tile(ic + 1, (ic + 1) & 1);
        const int cb = ic & 1;
        #pragma unroll
        for (int dy = 0; dy < 3; dy++)
            #pragma unroll
            for (int dx = 0; dx < 3; dx++)
                acc += sw[ic*9 + dy*3 + dx]*st[cb][ty + dy][tx + dx];
        __syncthreads();
    }
    out[(size_t)b*HW + (h0 + ty)*128 + (w0 + tx)] = acc;
}

extern "C" void kernel_launch(void* const* d_in, const int* in_sizes, int n_in,
                              void* d_out, int out_size)
{
    const float* x    = (const float*)d_in[0];
    const float* g_w  = (const float*)d_in[1];
    const float* g_b  = (const float*)d_in[2];
    const float* th_w = (const float*)d_in[3];
    const float* th_b = (const float*)d_in[4];
    const float* ph_w = (const float*)d_in[5];
    const float* ph_b = (const float*)d_in[6];
    const float* Ws_w = (const float*)d_in[7];
    const float* Ws_b = (const float*)d_in[8];
    const float* Wc_w = (const float*)d_in[9];
    const float* Wc_b = (const float*)d_in[10];
    const float* gs   = (const float*)d_in[11];
    const float* gc   = (const float*)d_in[12];
    const float* m1w  = (const float*)d_in[13];
    const float* m1b  = (const float*)d_in[14];
    const float* m2w  = (const float*)d_in[15];
    const float* m2b  = (const float*)d_in[16];
    float* out = (float*)d_out;   // logit [4*16384] then z [4*64*16384]

    cudaFuncSetAttribute(wgemm, cudaFuncAttributeMaxDynamicSharedMemorySize, SMSZ);
    cudaFuncSetAttribute(fcgemm_tn, cudaFuncAttributeMaxDynamicSharedMemorySize, TSMSZ);

    float *XT, *TH, *PH, *GX, *GN, *P, *Lp, *Li, *YS, *FC, *YC;
    cudaGetSymbolAddress((void**)&XT, g_XT);
    cudaGetSymbolAddress((void**)&TH, g_TH);
    cudaGetSymbolAddress((void**)&PH, g_PH);
    cudaGetSymbolAddress((void**)&GX, g_GX);
    cudaGetSymbolAddress((void**)&GN, g_GN);
    cudaGetSymbolAddress((void**)&P,  g_P);
    cudaGetSymbolAddress((void**)&Lp, g_Lp);
    cudaGetSymbolAddress((void**)&Li, g_Li);
    cudaGetSymbolAddress((void**)&YS, g_YS);
    cudaGetSymbolAddress((void**)&FC, g_FC);
    cudaGetSymbolAddress((void**)&YC, g_YC);

    transpose_kernel<<<dim3(128, 8, 4), dim3(32, 8)>>>(x);

    // theta/phi/g_n [n][c] = XT @ W^T + bias(col)
    wgemm<<<dim3(32, 2, 4), 128, SMSZ>>>(XT, IC, (size_t)NN*IC,
        th_w, IC, 0, TH, IC, (size_t)NN*IC, IC, th_b, nullptr, 0);
    wgemm<<<dim3(32, 2, 4), 128, SMSZ>>>(XT, IC, (size_t)NN*IC,
        ph_w, IC, 0, PH, IC, (size_t)NN*IC, IC, ph_b, nullptr, 0);
    wgemm<<<dim3(32, 2, 4), 128, SMSZ>>>(XT, IC, (size_t)NN*IC,
        g_w, IC, 0, GN, IC, (size_t)NN*IC, IC, g_b, nullptr, 0);
    // g [o][n] = g_w @ XT^T + bias(row)
    wgemm<<<dim3(2, 32, 4), 128, SMSZ>>>(g_w, IC, 0,
        XT, IC, (size_t)NN*IC, GX, NN, (size_t)IC*NN, IC, g_b, nullptr, 1);

    fcgemm_tn<<<dim3(2, 2, 64), 128, TSMSZ>>>();
    fcsoftmax_kernel<<<dim3(256, 4), 256>>>();

    // P = exp(TH @ PH^T), fused row partial sums
    wgemm<<<dim3(32, 32, 4), 128, SMSZ>>>(TH, IC, (size_t)NN*IC,
        PH, IC, (size_t)NN*IC, P, NN, (size_t)NN*NN, IC, nullptr, Lp, 2);
    lreduce_kernel<<<dim3(16, 4), 256>>>();
    // y_s = (P @ GX^T) * Li[row]
    wgemm<<<dim3(32, 2, 4), 128, SMSZ>>>(P, NN, (size_t)NN*NN,
        GX, NN, (size_t)IC*NN, YS, IC, (size_t)NN*IC, NN, Li, nullptr, 3);
    // y_c = GN @ (f_c^T)^T
    wgemm<<<dim3(32, 2, 4), 128, SMSZ>>>(GN, IC, (size_t)NN*IC,
        FC, IC, (size_t)IC*IC, YC, IC, (size_t)NN*IC, IC, nullptr, nullptr, 4);

    zmix_kernel<<<dim3(256, 4), 256>>>(x, Ws_w, Ws_b, Wc_w, Wc_b, gs, gc, out + 65536);
    conv1_kernel<<<dim3(4, 16, 4), dim3(32, 8)>>>(m1w, m1b);
    conv2_kernel<<<dim3(4, 16, 4), dim3(32, 8)>>>(m2w, m2b, out);
}

// round 14
// speedup vs baseline: 1.7452x; 1.1173x over previous
#include <cuda_runtime.h>
#include <cuda_bf16.h>
#include <cstdint>

#define BB 4
#define IC 256
#define NN 4096
#define HW 16384

// ---- scratch ----
__device__ __align__(16) float g_XT[BB*NN*IC];   // x^T   [b][n][c]
__device__ __align__(16) float g_TH[BB*NN*IC];   // theta [b][n][c]
__device__ __align__(16) float g_PH[BB*NN*IC];   // phi   [b][n][c]
__device__ __align__(16) __nv_bfloat16 g_GXb[BB*IC*NN];       // g [b][o][n] bf16
__device__ __align__(16) float g_GN[BB*NN*IC];   // g     [b][n][o]
__device__ __align__(16) __nv_bfloat16 g_Pb[(size_t)BB*NN*NN];// exp(S) bf16
__device__ __align__(16) float g_Lp[BB*32*NN];
__device__ __align__(16) float g_Li[BB*NN];
__device__ __align__(16) float g_YS[BB*NN*IC];
__device__ __align__(16) float g_FCP[BB*16*IC*IC];
__device__ __align__(16) float g_FC[BB*IC*IC];   // f_c^T [b][d][c]
__device__ __align__(16) float g_YC[BB*NN*IC];
__device__ __align__(16) float g_Z [BB*64*HW];
__device__ __align__(16) float g_H [BB*16*HW];

static __device__ __forceinline__ uint32_t smem_u32(const void* p) {
    uint32_t a;
    asm("{ .reg .u64 t; cvta.to.shared.u64 t, %1; cvt.u32.u64 %0, t; }" : "=r"(a) : "l"(p));
    return a;
}
static __device__ __forceinline__ void mma8(float* d, const uint32_t* a, const uint32_t* b) {
    asm volatile(
        "mma.sync.aligned.m16n8k8.row.col.f32.tf32.tf32.f32 "
        "{%0,%1,%2,%3}, {%4,%5,%6,%7}, {%8,%9}, {%0,%1,%2,%3};"
        : "+f"(d[0]), "+f"(d[1]), "+f"(d[2]), "+f"(d[3])
        : "r"(a[0]), "r"(a[1]), "r"(a[2]), "r"(a[3]), "r"(b[0]), "r"(b[1]));
}
static __device__ __forceinline__ void mma16(float* d, const uint32_t* a, const uint32_t* b) {
    asm volatile(
        "mma.sync.aligned.m16n8k16.row.col.f32.bf16.bf16.f32 "
        "{%0,%1,%2,%3}, {%4,%5,%6,%7}, {%8,%9}, {%0,%1,%2,%3};"
        : "+f"(d[0]), "+f"(d[1]), "+f"(d[2]), "+f"(d[3])
        : "r"(a[0]), "r"(a[1]), "r"(a[2]), "r"(a[3]), "r"(b[0]), "r"(b[1]));
}
static __device__ __forceinline__ __nv_bfloat162 pk2(float lo, float hi) {
    __nv_bfloat162 h;
    h.x = __float2bfloat16_rn(lo);
    h.y = __float2bfloat16_rn(hi);
    return h;
}
#define CPA(dst, src) asm volatile("cp.async.cg.shared.global [%0], [%1], 16;" :: "r"(dst), "l"(src))
#define CPC()  asm volatile("cp.async.commit_group;" ::: "memory")
#define CPW1() asm volatile("cp.async.wait_group 1;" ::: "memory")

// wgemm SMEM: A stages 0/18432/36864, B @55296+...
#define STG 18432u
#define BOFF 55296u
#define SMSZ 110592

// ============================================================
// wgemm (fp32 in, tf32 MMA): 256 thr, 8 warps 32x64, CTA 128x128, 3-stage
// D = A @ B^T; A [M][K] ldA, B [N][K] ldB, K%32==0
// mode 0: fp32 out +aux[col];  1: bf16 out +aux[row];
// mode 2: bf16 out = exp(S), row partsums->aux2;  4: fp32 plain
// ============================================================
__global__ __launch_bounds__(256, 2) void wgemm(
    const float* __restrict__ A, int ldA, size_t Abs,
    const float* __restrict__ B, int ldB, size_t Bbs,
    void* __restrict__ D, int ldD, size_t Dbs,
    int K, const float* __restrict__ aux, float* __restrict__ aux2, int mode)
{
    extern __shared__ __align__(16) char wsm[];
    __shared__ float sred[2][128];
    const uint32_t sb = smem_u32(wsm);
    const uint32_t* uS = (const uint32_t*)wsm;
    const int tid = threadIdx.x, wid = tid >> 5, lane = tid & 31;
    const int gid = lane >> 2, tig = lane & 3;
    const int wm = wid & 3, wn = wid >> 2;
    const float* At = A + (size_t)blockIdx.z*Abs + (size_t)blockIdx.x*128*ldA;
    const float* Bt = B + (size_t)blockIdx.z*Bbs + (size_t)blockIdx.y*128*ldB;
    float acc[2][8][4] = {};
    const int NC = K >> 5;

    auto load_chunk = [&](int kc) {
        const uint32_t so = (uint32_t)(kc % 3)*STG;
        const int ko = kc*32;
        #pragma unroll
        for (int l = 0; l < 4; l++) {
            int f = l*256 + tid, r = f >> 3, c4 = (f & 7)*4;
            CPA(sb + so + (uint32_t)(r*36 + c4)*4, At + (size_t)r*ldA + ko + c4);
            CPA(sb + BOFF + so + (uint32_t)(r*36 + c4)*4, Bt + (size_t)r*ldB + ko + c4);
        }
    };
    load_chunk(0); CPC();
    load_chunk(1); CPC();

    #pragma unroll 1
    for (int kc = 0; kc < NC; kc++) {
        CPW1();
        __syncthreads();
        if (kc + 2 < NC) { load_chunk(kc + 2); CPC(); }
        const int st = kc % 3;
        const uint32_t* uA = uS + st*4608;
        const uint32_t* uB = uS + 13824 + st*4608;
        #pragma unroll
        for (int ks = 0; ks < 4; ks++) {
            const int kk = ks*8;
            uint32_t af[2][4], bf[8][2];
            #pragma unroll
            for (int i = 0; i < 2; i++) {
                const int rb = wm*32 + i*16;
                af[i][0] = uA[(rb+gid)*36 + kk+tig];
                af[i][1] = uA[(rb+8+gid)*36 + kk+tig];
                af[i][2] = uA[(rb+gid)*36 + kk+tig+4];
                af[i][3] = uA[(rb+8+gid)*36 + kk+tig+4];
            }
            #pragma unroll
            for (int j = 0; j < 8; j++) {
                const int nb = wn*64 + j*8 + gid;
                bf[j][0] = uB[nb*36 + kk+tig];
                bf[j][1] = uB[nb*36 + kk+tig+4];
            }
            #pragma unroll
            for (int i = 0; i < 2; i++)
                #pragma unroll
                for (int j = 0; j < 8; j++)
                    mma8(acc[i][j], af[i], bf[j]);
        }
    }

    float* Df = (float*)D + (size_t)blockIdx.z*Dbs
              + (size_t)blockIdx.x*128*ldD + blockIdx.y*128;
    __nv_bfloat16* Dh = (__nv_bfloat16*)D + (size_t)blockIdx.z*Dbs
              + (size_t)blockIdx.x*128*ldD + blockIdx.y*128;
    #pragma unroll
    for (int i = 0; i < 2; i++) {
        const int r0 = wm*32 + i*16 + gid, r1 = r0 + 8;
        float add0 = 0.f, add1 = 0.f;
        if (mode == 1) {
            add0 = aux[blockIdx.x*128 + r0];
            add1 = aux[blockIdx.x*128 + r1];
        }
        float ls0 = 0.f, ls1 = 0.f;
        #pragma unroll
        for (int j = 0; j < 8; j++) {
            const int cl = wn*64 + j*8 + 2*tig;
            float v0 = acc[i][j][0], v1 = acc[i][j][1];
            float v2 = acc[i][j][2], v3 = acc[i][j][3];
            if (mode == 0) {
                const int cg = blockIdx.y*128 + cl;
                float a0 = __ldg(&aux[cg]), a1 = __ldg(&aux[cg+1]);
                v0 += a0; v1 += a1; v2 += a0; v3 += a1;
            } else if (mode == 1) {
                v0 += add0; v1 += add0; v2 += add1; v3 += add1;
            } else if (mode == 2) {
                v0 = __expf(v0); v1 = __expf(v1);
                v2 = __expf(v2); v3 = __expf(v3);
                ls0 += v0 + v1; ls1 += v2 + v3;
            }
            if (mode == 1 || mode == 2) {
                *(__nv_bfloat162*)(Dh + (size_t)r0*ldD + cl) = pk2(v0, v1);
                *(__nv_bfloat162*)(Dh + (size_t)r1*ldD + cl) = pk2(v2, v3);
            } else {
                *(float2*)(Df + (size_t)r0*ldD + cl) = make_float2(v0, v1);
                *(float2*)(Df + (size_t)r1*ldD + cl) = make_float2(v2, v3);
            }
        }
        if (mode == 2) {
            ls0 += __shfl_xor_sync(0xffffffffu, ls0, 1);
            ls0 += __shfl_xor_sync(0xffffffffu, ls0, 2);
            ls1 += __shfl_xor_sync(0xffffffffu, ls1, 1);
            ls1 += __shfl_xor_sync(0xffffffffu, ls1, 2);
            if (tig == 0) { sred[wn][r0] = ls0; sred[wn][r1] = ls1; }
        }
    }
    if (mode == 2) {
        __syncthreads();
        if (tid < 128)
            aux2[((size_t)blockIdx.z*gridDim.y + blockIdx.y)*NN + blockIdx.x*128 + tid]
                = sred[0][tid] + sred[1][tid];
    }
}

// ============================================================
// bgemm (bf16 in, m16n8k16): y_s = (Pb @ GXb^T) * Li[row]
// 256 thr, 8 warps 32x64, CTA 128x128, 3-stage; K%32==0
// SMEM rows: 20 uint32 = 80 B (16B-aligned for cp.async)
// ============================================================
#define BSTG 10240u
#define BBOFF 30720u
#define BSMSZ 61440

__global__ __launch_bounds__(256, 2) void bgemm(
    const __nv_bfloat16* __restrict__ A, int ldA, size_t Abs,
    const __nv_bfloat16* __restrict__ B, int ldB, size_t Bbs,
    float* __restrict__ D, int ldD, size_t Dbs,
    int K, const float* __restrict__ aux)
{
    extern __shared__ __align__(16) char wsm[];
    const uint32_t sb = smem_u32(wsm);
    const uint32_t* uS = (const uint32_t*)wsm;
    const int tid = threadIdx.x, wid = tid >> 5, lane = tid & 31;
    const int gid = lane >> 2, tig = lane & 3;
    const int wm = wid & 3, wn = wid >> 2;
    const __nv_bfloat16* At = A + (size_t)blockIdx.z*Abs + (size_t)blockIdx.x*128*ldA;
    const __nv_bfloat16* Bt = B + (size_t)blockIdx.z*Bbs + (size_t)blockIdx.y*128*ldB;
    float acc[2][8][4] = {};
    const int NC = K >> 5;

    auto load_chunk = [&](int kc) {
        const uint32_t so = (uint32_t)(kc % 3)*BSTG;
        const int ko = kc*32;
        #pragma unroll
        for (int l = 0; l < 2; l++) {
            int f = l*256 + tid, r = f >> 2, sg = f & 3;
            CPA(sb + so + (uint32_t)(r*20 + sg*4)*4, At + (size_t)r*ldA + ko + sg*8);
            CPA(sb + BBOFF + so + (uint32_t)(r*20 + sg*4)*4, Bt + (size_t)r*ldB + ko + sg*8);
        }
    };
    load_chunk(0); CPC();
    load_chunk(1); CPC();

    #pragma unroll 1
    for (int kc = 0; kc < NC; kc++) {
        CPW1();
        __syncthreads();
        if (kc + 2 < NC) { load_chunk(kc + 2); CPC(); }
        const int st = kc % 3;
        const uint32_t* uA = uS + st*2560;
        const uint32_t* uB = uS + 7680 + st*2560;
        #pragma unroll
        for (int ks = 0; ks < 2; ks++) {
            const int kk = ks*8;
            uint32_t af[2][4], bf[8][2];
            #pragma unroll
            for (int i = 0; i < 2; i++) {
                const int rb = wm*32 + i*16;
                af[i][0] = uA[(rb+gid)*20 + kk+tig];
                af[i][1] = uA[(rb+8+gid)*20 + kk+tig];
                af[i][2] = uA[(rb+gid)*20 + kk+tig+4];
                af[i][3] = uA[(rb+8+gid)*20 + kk+tig+4];
            }
            #pragma unroll
            for (int j = 0; j < 8; j++) {
                const int nb = wn*64 + j*8 + gid;
                bf[j][0] = uB[nb*20 + kk+tig];
                bf[j][1] = uB[nb*20 + kk+tig+4];
            }
            #pragma unroll
            for (int i = 0; i < 2; i++)
                #pragma unroll
                for (int j = 0; j < 8; j++)
                    mma16(acc[i][j], af[i], bf[j]);
        }
    }

    float* Dt = D + (size_t)blockIdx.z*Dbs + (size_t)blockIdx.x*128*ldD + blockIdx.y*128;
    #pragma unroll
    for (int i = 0; i < 2; i++) {
        const int r0 = wm*32 + i*16 + gid, r1 = r0 + 8;
        const float m0 = aux[(size_t)blockIdx.z*NN + blockIdx.x*128 + r0];
        const float m1 = aux[(size_t)blockIdx.z*NN + blockIdx.x*128 + r1];
        #pragma unroll
        for (int j = 0; j < 8; j++) {
            const int cl = wn*64 + j*8 + 2*tig;
            *(float2*)(Dt + (size_t)r0*ldD + cl) =
                make_float2(acc[i][j][0]*m0, acc[i][j][1]*m0);
            *(float2*)(Dt + (size_t)r1*ldD + cl) =
                make_float2(acc[i][j][2]*m1, acc[i][j][3]*m1);
        }
    }
}

// ============================================================
// TN tensor GEMM for f_c (tf32): grid (2,2,64), 128 thr, split-K x16
// ============================================================
#define TSTG 17408u
#define TBOFF 52224u
#define TSMSZ 104448

__global__ __launch_bounds__(128, 2) void fcgemm_tn()
{
    extern __shared__ __align__(16) char wsm[];
    const uint32_t sb = smem_u32(wsm);
    const uint32_t* uS = (const uint32_t*)wsm;
    const int tid = threadIdx.x, wid = tid >> 5, lane = tid & 31;
    const int gid = lane >> 2, tig = lane & 3;
    const int wm = wid & 1, wn = wid >> 1;
    const int bz = blockIdx.z, b = bz >> 4, ks = bz & 15;
    const float* At = g_TH + ((size_t)b*NN + ks*256)*IC + blockIdx.x*128;
    const float* Bt = g_PH + ((size_t)b*NN + ks*256)*IC + blockIdx.y*128;
    float acc[4][8][4] = {};

    auto load_chunk = [&](int kc) {
        const uint32_t so = (uint32_t)(kc % 3)*TSTG;
        const size_t ro = (size_t)(kc*32)*IC;
        #pragma unroll
        for (int l = 0; l < 8; l++) {
            int f = l*128 + tid, kr = f >> 5, c4 = (f & 31)*4;
            CPA(sb + so + (uint32_t)(kr*136 + c4)*4, At + ro + (size_t)kr*IC + c4);
            CPA(sb + TBOFF + so + (uint32_t)(kr*136 + c4)*4, Bt + ro + (size_t)kr*IC + c4);
        }
    };
    load_chunk(0); CPC();
    load_chunk(1); CPC();

    #pragma unroll 1
    for (int kc = 0; kc < 8; kc++) {
        CPW1();
        __syncthreads();
        if (kc + 2 < 8) { load_chunk(kc + 2); CPC(); }
        const int st = kc % 3;
        const uint32_t* uA = uS + st*4352;
        const uint32_t* uB = uS + 13056 + st*4352;
        #pragma unroll
        for (int ksl = 0; ksl < 4; ksl++) {
            const int kk = ksl*8;
            uint32_t af[4][4], bf[8][2];
            #pragma unroll
            for (int i = 0; i < 4; i++) {
                const int rb = wm*64 + i*16;
                af[i][0] = uA[(kk+tig)*136 + rb+gid];
                af[i][1] = uA[(kk+tig)*136 + rb+8+gid];
                af[i][2] = uA[(kk+tig+4)*136 + rb+gid];
                af[i][3] = uA[(kk+tig+4)*136 + rb+8+gid];
            }
            #pragma unroll
            for (int j = 0; j < 8; j++) {
                const int nb = wn*64 + j*8 + gid;
                bf[j][0] = uB[(kk+tig)*136 + nb];
                bf[j][1] = uB[(kk+tig+4)*136 + nb];
            }
            #pragma unroll
            for (int i = 0; i < 4; i++)
                #pragma unroll
                for (int j = 0; j < 8; j++)
                    mma8(acc[i][j], af[i], bf[j]);
        }
    }
    float* Dt = g_FCP + ((size_t)bz*IC + blockIdx.x*128)*IC + blockIdx.y*128;
    #pragma unroll
    for (int i = 0; i < 4; i++) {
        const int r0 = wm*64 + i*16 + gid, r1 = r0 + 8;
        #pragma unroll
        for (int j = 0; j < 8; j++) {
            const int cl = wn*64 + j*8 + 2*tig;
            *(float2*)(Dt + (size_t)r0*IC + cl) = make_float2(acc[i][j][0], acc[i][j][1]);
            *(float2*)(Dt + (size_t)r1*IC + cl) = make_float2(acc[i][j][2], acc[i][j][3]);
        }
    }
}

// x[b][c][n] -> g_XT[b][n][c]
__global__ __launch_bounds__(256) void transpose_kernel(const float* __restrict__ x)
{
    __shared__ float t[32][33];
    const int b = blockIdx.z, n0 = blockIdx.x*32, c0 = blockIdx.y*32;
    const int tx = threadIdx.x, ty = threadIdx.y;
    #pragma unroll
    for (int i = 0; i < 4; i++)
        t[ty + i*8][tx] = x[(size_t)b*IC*NN + (size_t)(c0 + ty + i*8)*NN + n0 + tx];
    __syncthreads();
    #pragma unroll
    for (int i = 0; i < 4; i++)
        g_XT[(size_t)b*NN*IC + (size_t)(n0 + ty + i*8)*IC + c0 + tx] = t[tx][ty + i*8];
}

// g_Li = 1/rowsum; grid (16,4)
__global__ __launch_bounds__(256) void lreduce_kernel()
{
    const int b = blockIdx.y, n = blockIdx.x*256 + threadIdx.x;
    float s = 0.f;
    #pragma unroll
    for (int mt = 0; mt < 32; mt++) s += g_Lp[((size_t)b*32 + mt)*NN + n];
    g_Li[(size_t)b*NN + n] = 1.0f / s;
}

// reduce split-K x16 + softmax over d; writes f_c^T[d][c]; grid (256,4)
__global__ __launch_bounds__(256) void fcsoftmax_kernel()
{
    __shared__ float red[256];
    const int b = blockIdx.y, c = blockIdx.x, tid = threadIdx.x;
    float v = 0.f;
    #pragma unroll
    for (int ks = 0; ks < 16; ks++)
        v += g_FCP[(((size_t)b*16 + ks)*IC + c)*IC + tid];
    red[tid] = v; __syncthreads();
    for (int s = 128; s > 0; s >>= 1) {
        if (tid < s) red[tid] = fmaxf(red[tid], red[tid + s]);
        __syncthreads();
    }
    float m = red[0]; __syncthreads();
    float e = __expf(v - m);
    red[tid] = e; __syncthreads();
    for (int s = 128; s > 0; s >>= 1) {
        if (tid < s) red[tid] += red[tid + s];
        __syncthreads();
    }
    g_FC[(size_t)b*IC*IC + (size_t)tid*IC + c] = e / red[0];
}

// z = x + gs*(Ws@ys+b) + gc*(Wc@yc+b); grid (256,4)
__global__ __launch_bounds__(256) void zmix_kernel(
    const float* __restrict__ x,
    const float* __restrict__ Ws_w, const float* __restrict__ Ws_b,
    const float* __restrict__ Wc_w, const float* __restrict__ Wc_b,
    const float* __restrict__ gs, const float* __restrict__ gc,
    float* __restrict__ zout)
{
    __shared__ float sW[64][64];
    __shared__ float sD[64][65];
    const int b = blockIdx.y, p0 = blockIdx.x*64;
    const int tid = threadIdx.x, tx = tid & 63, ty = tid >> 6;
    float accs[16] = {}, accc[16] = {};
    #pragma unroll
    for (int l = 0; l < 16; l++) {
        int idx = l*256 + tid;
        sW[idx >> 6][idx & 63] = Ws_w[idx];
        int i = idx >> 6, px = idx & 63;
        int p = p0 + px, h = p >> 7, w = p & 127;
        int o = 4*i + (h >> 5), n = ((h & 31) << 7) | w;
        sD[i][px] = g_YS[((size_t)(b << 12) + n)*IC + o];
    }
    __syncthreads();
    #pragma unroll 4
    for (int i = 0; i < 64; i++) {
        float yv = sD[i][tx];
        #pragma unroll
        for (int k = 0; k < 16; k++) accs[k] += sW[16*ty + k][i]*yv;
    }
    __syncthreads();
    #pragma unroll
    for (int l = 0; l < 16; l++) {
        int idx = l*256 + tid;
        sW[idx >> 6][idx & 63] = Wc_w[idx];
        int i = idx >> 6, px = idx & 63;
        int p = p0 + px, h = p >> 7, w = p & 127;
        int n = (i << 6) + (h >> 1), d = ((h & 1) << 7) | w;
        sD[i][px] = g_YC[((size_t)(b << 12) + n)*IC + d];
    }
    __syncthreads();
    #pragma unroll 4
    for (int i = 0; i < 64; i++) {
        float cv = sD[i][tx];
        #pragma unroll
        for (int k = 0; k < 16; k++) accc[k] += sW[16*ty + k][i]*cv;
    }
    float gsv = gs[0], gcv = gc[0];
    int p = p0 + tx;
    #pragma unroll
    for (int k = 0; k < 16; k++) {
        int oc = 16*ty + k;
        size_t idx = (size_t)(b*64 + oc)*HW + p;
        float z = x[idx] + gsv*(accs[k] + Ws_b[oc]) + gcv*(accc[k] + Wc_b[oc]);
        g_Z[idx] = z;
        zout[idx] = z;
    }
}

// conv3x3 64->16 + relu, double-buffered; grid (4,16,4), block (32,8)
__global__ __launch_bounds__(256) void conv1_kernel(
    const float* __restrict__ m1w, const float* __restrict__ m1b)
{
    __shared__ float sw[16*64*9];
    __shared__ float st[2][10][36];
    const int b = blockIdx.z, h0 = blockIdx.y*8, w0 = blockIdx.x*32;
    const int tx = threadIdx.x, ty = threadIdx.y, tid = ty*32 + tx;
    for (int i = tid; i < 9216; i += 256) sw[i] = m1w[i];
    float acc[16];
    #pragma unroll
    for (int oc = 0; oc < 16; oc++) acc[oc] = m1b[oc];

    auto load_tile = [&](int ic, int buf) {
        const float* zp = g_Z + (size_t)(b*64 + ic)*HW;
        for (int l = tid; l < 340; l += 256) {
            int yy = l / 34, xx = l % 34;
            int hh = h0 - 1 + yy, ww = w0 - 1 + xx;
            st[buf][yy][xx] = (hh >= 0 && hh < 128 && ww >= 0 && ww < 128)
                              ? zp[hh*128 + ww] : 0.f;
        }
    };
    load_tile(0, 0);
    __syncthreads();
    for (int ic = 0; ic < 64; ic++) {
        if (ic + 1 < 64) load_tile(ic + 1, (ic + 1) & 1);
        const int cb = ic & 1;
        #pragma unroll
        for (int dy = 0; dy < 3; dy++)
            #pragma unroll
            for (int dx = 0; dx < 3; dx++) {
                float zv = st[cb][ty + dy][tx + dx];
                #pragma unroll
                for (int oc = 0; oc < 16; oc++)
                    acc[oc] += sw[(oc*64 + ic)*9 + dy*3 + dx]*zv;
            }
        __syncthreads();
    }
    int h = h0 + ty, w = w0 + tx;
    #pragma unroll
    for (int oc = 0; oc < 16; oc++)
        g_H[(size_t)(b*16 + oc)*HW + h*128 + w] = fmaxf(acc[oc], 0.f);
}

// conv3x3 16->1, double-buffered; grid (4,16,4), block (32,8)
__global__ __launch_bounds__(256) void conv2_kernel(
    const float* __restrict__ m2w, const float* __restrict__ m2b,
    float* __restrict__ out)
{
    __shared__ float sw[144];
    __shared__ float st[2][10][36];
    const int b = blockIdx.z, h0 = blockIdx.y*8, w0 = blockIdx.x*32;
    const int tx = threadIdx.x, ty = threadIdx.y, tid = ty*32 + tx;
    if (tid < 144) sw[tid] = m2w[tid];
    float acc = m2b[0];
    auto load_tile = [&](int ic, int buf) {
        const float* hp = g_H + (size_t)(b*16 + ic)*HW;
        for (int l = tid; l < 340; l += 256) {
            int yy = l / 34, xx = l % 34;
            int hh = h0 - 1 + yy, ww = w0 - 1 + xx;
            st[buf][yy][xx] = (hh >= 0 && hh < 128 && ww >= 0 && ww < 128)
                              ? hp[hh*128 + ww] : 0.f;
        }
    };
    load_tile(0, 0);
    __syncthreads();
    for (int ic = 0; ic < 16; ic++) {
        if (ic + 1 < 16) load_tile(ic + 1, (ic + 1) & 1);
        const int cb = ic & 1;
        #pragma unroll
        for (int dy = 0; dy < 3; dy++)
            #pragma unroll
            for (int dx = 0; dx < 3; dx++)
                acc += sw[ic*9 + dy*3 + dx]*st[cb][ty + dy][tx + dx];
        __syncthreads();
    }
    out[(size_t)b*HW + (h0 + ty)*128 + (w0 + tx)] = acc;
}

extern "C" void kernel_launch(void* const* d_in, const int* in_sizes, int n_in,
                              void* d_out, int out_size)
{
    const float* x    = (const float*)d_in[0];
    const float* g_w  = (const float*)d_in[1];
    const float* g_b  = (const float*)d_in[2];
    const float* th_w = (const float*)d_in[3];
    const float* th_b = (const float*)d_in[4];
    const float* ph_w = (const float*)d_in[5];
    const float* ph_b = (const float*)d_in[6];
    const float* Ws_w = (const float*)d_in[7];
    const float* Ws_b = (const float*)d_in[8];
    const float* Wc_w = (const float*)d_in[9];
    const float* Wc_b = (const float*)d_in[10];
    const float* gs   = (const float*)d_in[11];
    const float* gc   = (const float*)d_in[12];
    const float* m1w  = (const float*)d_in[13];
    const float* m1b  = (const float*)d_in[14];
    const float* m2w  = (const float*)d_in[15];
    const float* m2b  = (const float*)d_in[16];
    float* out = (float*)d_out;   // logit [4*16384] then z [4*64*16384]

    cudaFuncSetAttribute(wgemm, cudaFuncAttributeMaxDynamicSharedMemorySize, SMSZ);
    cudaFuncSetAttribute(bgemm, cudaFuncAttributeMaxDynamicSharedMemorySize, BSMSZ);
    cudaFuncSetAttribute(fcgemm_tn, cudaFuncAttributeMaxDynamicSharedMemorySize, TSMSZ);

    float *XT, *TH, *PH, *GN, *Lp, *Li, *YS, *FC, *YC;
    __nv_bfloat16 *Pb, *GXb;
    cudaGetSymbolAddress((void**)&XT, g_XT);
    cudaGetSymbolAddress((void**)&TH, g_TH);
    cudaGetSymbolAddress((void**)&PH, g_PH);
    cudaGetSymbolAddress((void**)&GXb, g_GXb);
    cudaGetSymbolAddress((void**)&GN, g_GN);
    cudaGetSymbolAddress((void**)&Pb, g_Pb);
    cudaGetSymbolAddress((void**)&Lp, g_Lp);
    cudaGetSymbolAddress((void**)&Li, g_Li);
    cudaGetSymbolAddress((void**)&YS, g_YS);
    cudaGetSymbolAddress((void**)&FC, g_FC);
    cudaGetSymbolAddress((void**)&YC, g_YC);

    transpose_kernel<<<dim3(128, 8, 4), dim3(32, 8)>>>(x);

    // theta/phi/g_n [n][c] = XT @ W^T + bias(col), fp32 out
    wgemm<<<dim3(32, 2, 4), 256, SMSZ>>>(XT, IC, (size_t)NN*IC,
        th_w, IC, 0, TH, IC, (size_t)NN*IC, IC, th_b, nullptr, 0);
    wgemm<<<dim3(32, 2, 4), 256, SMSZ>>>(XT, IC, (size_t)NN*IC,
        ph_w, IC, 0, PH, IC, (size_t)NN*IC, IC, ph_b, nullptr, 0);
    wgemm<<<dim3(32, 2, 4), 256, SMSZ>>>(XT, IC, (size_t)NN*IC,
        g_w, IC, 0, GN, IC, (size_t)NN*IC, IC, g_b, nullptr, 0);
    // g [o][n] = g_w @ XT^T + bias(row), bf16 out
    wgemm<<<dim3(2, 32, 4), 256, SMSZ>>>(g_w, IC, 0,
        XT, IC, (size_t)NN*IC, GXb, NN, (size_t)IC*NN, IC, g_b, nullptr, 1);

    fcgemm_tn<<<dim3(2, 2, 64), 128, TSMSZ>>>();
    fcsoftmax_kernel<<<dim3(256, 4), 256>>>();

    // Pb = exp(TH @ PH^T) bf16, fused row partial sums
    wgemm<<<dim3(32, 32, 4), 256, SMSZ>>>(TH, IC, (size_t)NN*IC,
        PH, IC, (size_t)NN*IC, Pb, NN, (size_t)NN*NN, IC, nullptr, Lp, 2);
    lreduce_kernel<<<dim3(16, 4), 256>>>();
    // y_s = (Pb @ GXb^T) * Li[row], bf16 MMA
    bgemm<<<dim3(32, 2, 4), 256, BSMSZ>>>(Pb, NN, (size_t)NN*NN,
        GXb, NN, (size_t)IC*NN, YS, IC, (size_t)NN*IC, NN, Li);
    // y_c = GN @ (f_c^T)^T, fp32 out
    wgemm<<<dim3(32, 2, 4), 256, SMSZ>>>(GN, IC, (size_t)NN*IC,
        FC, IC, (size_t)IC*IC, YC, IC, (size_t)NN*IC, IC, nullptr, nullptr, 4);

    zmix_kernel<<<dim3(256, 4), 256>>>(x, Ws_w, Ws_b, Wc_w, Wc_b, gs, gc, out + 65536);
    conv1_kernel<<<dim3(4, 16, 4), dim3(32, 8)>>>(m1w, m1b);
    conv2_kernel<<<dim3(4, 16, 4), dim3(32, 8)>>>(m2w, m2b, out);
}

// round 15
// speedup vs baseline: 1.9721x; 1.1300x over previous
#include <cuda_runtime.h>
#include <cuda_bf16.h>
#include <cstdint>

#define BB 4
#define IC 256
#define NN 4096
#define HW 16384

// ---- scratch ----
__device__ __align__(16) float g_XT[BB*NN*IC];   // x^T   [b][n][c]
__device__ __align__(16) float g_TH[BB*NN*IC];   // theta [b][n][c] fp32 (for f_c)
__device__ __align__(16) float g_PH[BB*NN*IC];   // phi   [b][n][c] fp32 (for f_c)
__device__ __align__(16) __nv_bfloat16 g_THb[BB*NN*IC];       // theta bf16
__device__ __align__(16) __nv_bfloat16 g_PHb[BB*NN*IC];       // phi   bf16
__device__ __align__(16) __nv_bfloat16 g_GXb[BB*IC*NN];       // g [b][o][n] bf16
__device__ __align__(16) float g_GN[BB*NN*IC];   // g     [b][n][o]
__device__ __align__(16) __nv_bfloat16 g_Pb[(size_t)BB*NN*NN];// exp(S) bf16
__device__ __align__(16) float g_Lp[BB*32*NN];
__device__ __align__(16) float g_Li[BB*NN];
__device__ __align__(16) float g_YS[BB*NN*IC];
__device__ __align__(16) float g_FCP[BB*16*IC*IC];
__device__ __align__(16) float g_FC[BB*IC*IC];   // f_c^T [b][d][c]
__device__ __align__(16) float g_YC[BB*NN*IC];
__device__ __align__(16) float g_Z [BB*64*HW];
__device__ __align__(16) float g_H [BB*16*HW];

static __device__ __forceinline__ uint32_t smem_u32(const void* p) {
    uint32_t a;
    asm("{ .reg .u64 t; cvta.to.shared.u64 t, %1; cvt.u32.u64 %0, t; }" : "=r"(a) : "l"(p));
    return a;
}
static __device__ __forceinline__ void mma8(float* d, const uint32_t* a, const uint32_t* b) {
    asm volatile(
        "mma.sync.aligned.m16n8k8.row.col.f32.tf32.tf32.f32 "
        "{%0,%1,%2,%3}, {%4,%5,%6,%7}, {%8,%9}, {%0,%1,%2,%3};"
        : "+f"(d[0]), "+f"(d[1]), "+f"(d[2]), "+f"(d[3])
        : "r"(a[0]), "r"(a[1]), "r"(a[2]), "r"(a[3]), "r"(b[0]), "r"(b[1]));
}
static __device__ __forceinline__ void mma16(float* d, const uint32_t* a, const uint32_t* b) {
    asm volatile(
        "mma.sync.aligned.m16n8k16.row.col.f32.bf16.bf16.f32 "
        "{%0,%1,%2,%3}, {%4,%5,%6,%7}, {%8,%9}, {%0,%1,%2,%3};"
        : "+f"(d[0]), "+f"(d[1]), "+f"(d[2]), "+f"(d[3])
        : "r"(a[0]), "r"(a[1]), "r"(a[2]), "r"(a[3]), "r"(b[0]), "r"(b[1]));
}
static __device__ __forceinline__ __nv_bfloat162 pk2(float lo, float hi) {
    __nv_bfloat162 h;
    h.x = __float2bfloat16_rn(lo);
    h.y = __float2bfloat16_rn(hi);
    return h;
}
#define CPA(dst, src) asm volatile("cp.async.cg.shared.global [%0], [%1], 16;" :: "r"(dst), "l"(src))
#define CPC()  asm volatile("cp.async.commit_group;" ::: "memory")
#define CPW1() asm volatile("cp.async.wait_group 1;" ::: "memory")

// wgemm SMEM: A stages 0/18432/36864, B @55296+...
#define STG 18432u
#define BOFF 55296u
#define SMSZ 110592

// ============================================================
// wgemm (fp32 in, tf32 MMA): 256 thr, 8 warps 32x64, CTA 128x128, 3-stage
// mode 1: bf16 out +aux[row];  4: fp32 plain out
// ============================================================
__global__ __launch_bounds__(256, 2) void wgemm(
    const float* __restrict__ A, int ldA, size_t Abs,
    const float* __restrict__ B, int ldB, size_t Bbs,
    void* __restrict__ D, int ldD, size_t Dbs,
    int K, const float* __restrict__ aux, int mode)
{
    extern __shared__ __align__(16) char wsm[];
    const uint32_t sb = smem_u32(wsm);
    const uint32_t* uS = (const uint32_t*)wsm;
    const int tid = threadIdx.x, wid = tid >> 5, lane = tid & 31;
    const int gid = lane >> 2, tig = lane & 3;
    const int wm = wid & 3, wn = wid >> 2;
    const float* At = A + (size_t)blockIdx.z*Abs + (size_t)blockIdx.x*128*ldA;
    const float* Bt = B + (size_t)blockIdx.z*Bbs + (size_t)blockIdx.y*128*ldB;
    float acc[2][8][4] = {};
    const int NC = K >> 5;

    auto load_chunk = [&](int kc) {
        const uint32_t so = (uint32_t)(kc % 3)*STG;
        const int ko = kc*32;
        #pragma unroll
        for (int l = 0; l < 4; l++) {
            int f = l*256 + tid, r = f >> 3, c4 = (f & 7)*4;
            CPA(sb + so + (uint32_t)(r*36 + c4)*4, At + (size_t)r*ldA + ko + c4);
            CPA(sb + BOFF + so + (uint32_t)(r*36 + c4)*4, Bt + (size_t)r*ldB + ko + c4);
        }
    };
    load_chunk(0); CPC();
    load_chunk(1); CPC();

    #pragma unroll 1
    for (int kc = 0; kc < NC; kc++) {
        CPW1();
        __syncthreads();
        if (kc + 2 < NC) { load_chunk(kc + 2); CPC(); }
        const int st = kc % 3;
        const uint32_t* uA = uS + st*4608;
        const uint32_t* uB = uS + 13824 + st*4608;
        #pragma unroll
        for (int ks = 0; ks < 4; ks++) {
            const int kk = ks*8;
            uint32_t af[2][4], bf[8][2];
            #pragma unroll
            for (int i = 0; i < 2; i++) {
                const int rb = wm*32 + i*16;
                af[i][0] = uA[(rb+gid)*36 + kk+tig];
                af[i][1] = uA[(rb+8+gid)*36 + kk+tig];
                af[i][2] = uA[(rb+gid)*36 + kk+tig+4];
                af[i][3] = uA[(rb+8+gid)*36 + kk+tig+4];
            }
            #pragma unroll
            for (int j = 0; j < 8; j++) {
                const int nb = wn*64 + j*8 + gid;
                bf[j][0] = uB[nb*36 + kk+tig];
                bf[j][1] = uB[nb*36 + kk+tig+4];
            }
            #pragma unroll
            for (int i = 0; i < 2; i++)
                #pragma unroll
                for (int j = 0; j < 8; j++)
                    mma8(acc[i][j], af[i], bf[j]);
        }
    }

    float* Df = (float*)D + (size_t)blockIdx.z*Dbs
              + (size_t)blockIdx.x*128*ldD + blockIdx.y*128;
    __nv_bfloat16* Dh = (__nv_bfloat16*)D + (size_t)blockIdx.z*Dbs
              + (size_t)blockIdx.x*128*ldD + blockIdx.y*128;
    #pragma unroll
    for (int i = 0; i < 2; i++) {
        const int r0 = wm*32 + i*16 + gid, r1 = r0 + 8;
        float add0 = 0.f, add1 = 0.f;
        if (mode == 1) {
            add0 = aux[blockIdx.x*128 + r0];
            add1 = aux[blockIdx.x*128 + r1];
        }
        #pragma unroll
        for (int j = 0; j < 8; j++) {
            const int cl = wn*64 + j*8 + 2*tig;
            float v0 = acc[i][j][0] + add0, v1 = acc[i][j][1] + add0;
            float v2 = acc[i][j][2] + add1, v3 = acc[i][j][3] + add1;
            if (mode == 1) {
                *(__nv_bfloat162*)(Dh + (size_t)r0*ldD + cl) = pk2(v0, v1);
                *(__nv_bfloat162*)(Dh + (size_t)r1*ldD + cl) = pk2(v2, v3);
            } else {
                *(float2*)(Df + (size_t)r0*ldD + cl) = make_float2(v0, v1);
                *(float2*)(Df + (size_t)r1*ldD + cl) = make_float2(v2, v3);
            }
        }
    }
}

// ============================================================
// proj_all: theta/phi/g_n [n][c] = XT @ W^T + bias(col)
// grid (32 ntiles, 6 = sel*2+ot, 4 b); fp32 out; bf16 copy for sel<2
// ============================================================
__global__ __launch_bounds__(256, 2) void proj_all(
    const float* __restrict__ th_w, const float* __restrict__ ph_w,
    const float* __restrict__ gw,
    const float* __restrict__ th_b, const float* __restrict__ ph_b,
    const float* __restrict__ gb)
{
    extern __shared__ __align__(16) char wsm[];
    const uint32_t sb = smem_u32(wsm);
    const uint32_t* uS = (const uint32_t*)wsm;
    const int tid = threadIdx.x, wid = tid >> 5, lane = tid & 31;
    const int gid = lane >> 2, tig = lane & 3;
    const int wm = wid & 3, wn = wid >> 2;
    const int b = blockIdx.z, sel = blockIdx.y >> 1, ot = blockIdx.y & 1;
    const float* W = (sel == 0) ? th_w : (sel == 1) ? ph_w : gw;
    const float* bias = (sel == 0) ? th_b : (sel == 1) ? ph_b : gb;
    float* dst = (sel == 0) ? g_TH : (sel == 1) ? g_PH : g_GN;
    __nv_bfloat16* dstb = (sel == 0) ? g_THb : g_PHb;
    const float* At = g_XT + (size_t)b*NN*IC + (size_t)blockIdx.x*128*IC;
    const float* Bt = W + (size_t)ot*128*IC;
    float acc[2][8][4] = {};

    auto load_chunk = [&](int kc) {
        const uint32_t so = (uint32_t)(kc % 3)*STG;
        const int ko = kc*32;
        #pragma unroll
        for (int l = 0; l < 4; l++) {
            int f = l*256 + tid, r = f >> 3, c4 = (f & 7)*4;
            CPA(sb + so + (uint32_t)(r*36 + c4)*4, At + (size_t)r*IC + ko + c4);
            CPA(sb + BOFF + so + (uint32_t)(r*36 + c4)*4, Bt + (size_t)r*IC + ko + c4);
        }
    };
    load_chunk(0); CPC();
    load_chunk(1); CPC();
    #pragma unroll 1
    for (int kc = 0; kc < 8; kc++) {
        CPW1();
        __syncthreads();
        if (kc + 2 < 8) { load_chunk(kc + 2); CPC(); }
        const int st = kc % 3;
        const uint32_t* uA = uS + st*4608;
        const uint32_t* uB = uS + 13824 + st*4608;
        #pragma unroll
        for (int ks = 0; ks < 4; ks++) {
            const int kk = ks*8;
            uint32_t af[2][4], bf[8][2];
            #pragma unroll
            for (int i = 0; i < 2; i++) {
                const int rb = wm*32 + i*16;
                af[i][0] = uA[(rb+gid)*36 + kk+tig];
                af[i][1] = uA[(rb+8+gid)*36 + kk+tig];
                af[i][2] = uA[(rb+gid)*36 + kk+tig+4];
                af[i][3] = uA[(rb+8+gid)*36 + kk+tig+4];
            }
            #pragma unroll
            for (int j = 0; j < 8; j++) {
                const int nb = wn*64 + j*8 + gid;
                bf[j][0] = uB[nb*36 + kk+tig];
                bf[j][1] = uB[nb*36 + kk+tig+4];
            }
            #pragma unroll
            for (int i = 0; i < 2; i++)
                #pragma unroll
                for (int j = 0; j < 8; j++)
                    mma8(acc[i][j], af[i], bf[j]);
        }
    }
    const size_t base = (size_t)b*NN*IC + (size_t)blockIdx.x*128*IC + ot*128;
    float* Dt = dst + base;
    __nv_bfloat16* Db = dstb + base;
    #pragma unroll
    for (int i = 0; i < 2; i++) {
        const int r0 = wm*32 + i*16 + gid, r1 = r0 + 8;
        #pragma unroll
        for (int j = 0; j < 8; j++) {
            const int cl = wn*64 + j*8 + 2*tig;
            float a0 = __ldg(&bias[ot*128 + cl]), a1 = __ldg(&bias[ot*128 + cl + 1]);
            float v0 = acc[i][j][0] + a0, v1 = acc[i][j][1] + a1;
            float v2 = acc[i][j][2] + a0, v3 = acc[i][j][3] + a1;
            *(float2*)(Dt + (size_t)r0*IC + cl) = make_float2(v0, v1);
            *(float2*)(Dt + (size_t)r1*IC + cl) = make_float2(v2, v3);
            if (sel < 2) {
                *(__nv_bfloat162*)(Db + (size_t)r0*IC + cl) = pk2(v0, v1);
                *(__nv_bfloat162*)(Db + (size_t)r1*IC + cl) = pk2(v2, v3);
            }
        }
    }
}

// ============================================================
// bgemm (bf16 in, m16n8k16): 256 thr, 8 warps 32x64, CTA 128x128, 3-stage
// mode 2: bf16 out = exp(S), row partsums->aux2
// mode 3: fp32 out *aux[b*NN+row]
// SMEM rows: 20 uint32 = 80 B
// ============================================================
#define BSTG 10240u
#define BBOFF 30720u
#define BSMSZ 61440

__global__ __launch_bounds__(256, 2) void bgemm(
    const __nv_bfloat16* __restrict__ A, int ldA, size_t Abs,
    const __nv_bfloat16* __restrict__ B, int ldB, size_t Bbs,
    void* __restrict__ D, int ldD, size_t Dbs,
    int K, const float* __restrict__ aux, float* __restrict__ aux2, int mode)
{
    extern __shared__ __align__(16) char wsm[];
    __shared__ float sred[2][128];
    const uint32_t sb = smem_u32(wsm);
    const uint32_t* uS = (const uint32_t*)wsm;
    const int tid = threadIdx.x, wid = tid >> 5, lane = tid & 31;
    const int gid = lane >> 2, tig = lane & 3;
    const int wm = wid & 3, wn = wid >> 2;
    const __nv_bfloat16* At = A + (size_t)blockIdx.z*Abs + (size_t)blockIdx.x*128*ldA;
    const __nv_bfloat16* Bt = B + (size_t)blockIdx.z*Bbs + (size_t)blockIdx.y*128*ldB;
    float acc[2][8][4] = {};
    const int NC = K >> 5;

    auto load_chunk = [&](int kc) {
        const uint32_t so = (uint32_t)(kc % 3)*BSTG;
        const int ko = kc*32;
        #pragma unroll
        for (int l = 0; l < 2; l++) {
            int f = l*256 + tid, r = f >> 2, sg = f & 3;
            CPA(sb + so + (uint32_t)(r*20 + sg*4)*4, At + (size_t)r*ldA + ko + sg*8);
            CPA(sb + BBOFF + so + (uint32_t)(r*20 + sg*4)*4, Bt + (size_t)r*ldB + ko + sg*8);
        }
    };
    load_chunk(0); CPC();
    load_chunk(1); CPC();

    #pragma unroll 1
    for (int kc = 0; kc < NC; kc++) {
        CPW1();
        __syncthreads();
        if (kc + 2 < NC) { load_chunk(kc + 2); CPC(); }
        const int st = kc % 3;
        const uint32_t* uA = uS + st*2560;
        const uint32_t* uB = uS + 7680 + st*2560;
        #pragma unroll
        for (int ks = 0; ks < 2; ks++) {
            const int kk = ks*8;
            uint32_t af[2][4], bf[8][2];
            #pragma unroll
            for (int i = 0; i < 2; i++) {
                const int rb = wm*32 + i*16;
                af[i][0] = uA[(rb+gid)*20 + kk+tig];
                af[i][1] = uA[(rb+8+gid)*20 + kk+tig];
                af[i][2] = uA[(rb+gid)*20 + kk+tig+4];
                af[i][3] = uA[(rb+8+gid)*20 + kk+tig+4];
            }
            #pragma unroll
            for (int j = 0; j < 8; j++) {
                const int nb = wn*64 + j*8 + gid;
                bf[j][0] = uB[nb*20 + kk+tig];
                bf[j][1] = uB[nb*20 + kk+tig+4];
            }
            #pragma unroll
            for (int i = 0; i < 2; i++)
                #pragma unroll
                for (int j = 0; j < 8; j++)
                    mma16(acc[i][j], af[i], bf[j]);
        }
    }

    float* Df = (float*)D + (size_t)blockIdx.z*Dbs
              + (size_t)blockIdx.x*128*ldD + blockIdx.y*128;
    __nv_bfloat16* Dh = (__nv_bfloat16*)D + (size_t)blockIdx.z*Dbs
              + (size_t)blockIdx.x*128*ldD + blockIdx.y*128;
    #pragma unroll
    for (int i = 0; i < 2; i++) {
        const int r0 = wm*32 + i*16 + gid, r1 = r0 + 8;
        float m0 = 1.f, m1 = 1.f;
        if (mode == 3) {
            m0 = aux[(size_t)blockIdx.z*NN + blockIdx.x*128 + r0];
            m1 = aux[(size_t)blockIdx.z*NN + blockIdx.x*128 + r1];
        }
        float ls0 = 0.f, ls1 = 0.f;
        #pragma unroll
        for (int j = 0; j < 8; j++) {
            const int cl = wn*64 + j*8 + 2*tig;
            float v0 = acc[i][j][0], v1 = acc[i][j][1];
            float v2 = acc[i][j][2], v3 = acc[i][j][3];
            if (mode == 2) {
                v0 = __expf(v0); v1 = __expf(v1);
                v2 = __expf(v2); v3 = __expf(v3);
                ls0 += v0 + v1; ls1 += v2 + v3;
                *(__nv_bfloat162*)(Dh + (size_t)r0*ldD + cl) = pk2(v0, v1);
                *(__nv_bfloat162*)(Dh + (size_t)r1*ldD + cl) = pk2(v2, v3);
            } else {
                *(float2*)(Df + (size_t)r0*ldD + cl) =
                    make_float2(v0*m0, v1*m0);
                *(float2*)(Df + (size_t)r1*ldD + cl) =
                    make_float2(v2*m1, v3*m1);
            }
        }
        if (mode == 2) {
            ls0 += __shfl_xor_sync(0xffffffffu, ls0, 1);
            ls0 += __shfl_xor_sync(0xffffffffu, ls0, 2);
            ls1 += __shfl_xor_sync(0xffffffffu, ls1, 1);
            ls1 += __shfl_xor_sync(0xffffffffu, ls1, 2);
            if (tig == 0) { sred[wn][r0] = ls0; sred[wn][r1] = ls1; }
        }
    }
    if (mode == 2) {
        __syncthreads();
        if (tid < 128)
            aux2[((size_t)blockIdx.z*gridDim.y + blockIdx.y)*NN + blockIdx.x*128 + tid]
                = sred[0][tid] + sred[1][tid];
    }
}

// ============================================================
// TN tensor GEMM for f_c (tf32, fp32 inputs): grid (2,2,64), 128 thr
// ============================================================
#define TSTG 17408u
#define TBOFF 52224u
#define TSMSZ 104448

__global__ __launch_bounds__(128, 2) void fcgemm_tn()
{
    extern __shared__ __align__(16) char wsm[];
    const uint32_t sb = smem_u32(wsm);
    const uint32_t* uS = (const uint32_t*)wsm;
    const int tid = threadIdx.x, wid = tid >> 5, lane = tid & 31;
    const int gid = lane >> 2, tig = lane & 3;
    const int wm = wid & 1, wn = wid >> 1;
    const int bz = blockIdx.z, b = bz >> 4, ks = bz & 15;
    const float* At = g_TH + ((size_t)b*NN + ks*256)*IC + blockIdx.x*128;
    const float* Bt = g_PH + ((size_t)b*NN + ks*256)*IC + blockIdx.y*128;
    float acc[4][8][4] = {};

    auto load_chunk = [&](int kc) {
        const uint32_t so = (uint32_t)(kc % 3)*TSTG;
        const size_t ro = (size_t)(kc*32)*IC;
        #pragma unroll
        for (int l = 0; l < 8; l++) {
            int f = l*128 + tid, kr = f >> 5, c4 = (f & 31)*4;
            CPA(sb + so + (uint32_t)(kr*136 + c4)*4, At + ro + (size_t)kr*IC + c4);
            CPA(sb + TBOFF + so + (uint32_t)(kr*136 + c4)*4, Bt + ro + (size_t)kr*IC + c4);
        }
    };
    load_chunk(0); CPC();
    load_chunk(1); CPC();

    #pragma unroll 1
    for (int kc = 0; kc < 8; kc++) {
        CPW1();
        __syncthreads();
        if (kc + 2 < 8) { load_chunk(kc + 2); CPC(); }
        const int st = kc % 3;
        const uint32_t* uA = uS + st*4352;
        const uint32_t* uB = uS + 13056 + st*4352;
        #pragma unroll
        for (int ksl = 0; ksl < 4; ksl++) {
            const int kk = ksl*8;
            uint32_t af[4][4], bf[8][2];
            #pragma unroll
            for (int i = 0; i < 4; i++) {
                const int rb = wm*64 + i*16;
                af[i][0] = uA[(kk+tig)*136 + rb+gid];
                af[i][1] = uA[(kk+tig)*136 + rb+8+gid];
                af[i][2] = uA[(kk+tig+4)*136 + rb+gid];
                af[i][3] = uA[(kk+tig+4)*136 + rb+8+gid];
            }
            #pragma unroll
            for (int j = 0; j < 8; j++) {
                const int nb = wn*64 + j*8 + gid;
                bf[j][0] = uB[(kk+tig)*136 + nb];
                bf[j][1] = uB[(kk+tig+4)*136 + nb];
            }
            #pragma unroll
            for (int i = 0; i < 4; i++)
                #pragma unroll
                for (int j = 0; j < 8; j++)
                    mma8(acc[i][j], af[i], bf[j]);
        }
    }
    float* Dt = g_FCP + ((size_t)bz*IC + blockIdx.x*128)*IC + blockIdx.y*128;
    #pragma unroll
    for (int i = 0; i < 4; i++) {
        const int r0 = wm*64 + i*16 + gid, r1 = r0 + 8;
        #pragma unroll
        for (int j = 0; j < 8; j++) {
            const int cl = wn*64 + j*8 + 2*tig;
            *(float2*)(Dt + (size_t)r0*IC + cl) = make_float2(acc[i][j][0], acc[i][j][1]);
            *(float2*)(Dt + (size_t)r1*IC + cl) = make_float2(acc[i][j][2], acc[i][j][3]);
        }
    }
}

// x[b][c][n] -> g_XT[b][n][c]
__global__ __launch_bounds__(256) void transpose_kernel(const float* __restrict__ x)
{
    __shared__ float t[32][33];
    const int b = blockIdx.z, n0 = blockIdx.x*32, c0 = blockIdx.y*32;
    const int tx = threadIdx.x, ty = threadIdx.y;
    #pragma unroll
    for (int i = 0; i < 4; i++)
        t[ty + i*8][tx] = x[(size_t)b*IC*NN + (size_t)(c0 + ty + i*8)*NN + n0 + tx];
    __syncthreads();
    #pragma unroll
    for (int i = 0; i < 4; i++)
        g_XT[(size_t)b*NN*IC + (size_t)(n0 + ty + i*8)*IC + c0 + tx] = t[tx][ty + i*8];
}

// g_Li = 1/rowsum; grid (16,4)
__global__ __launch_bounds__(256) void lreduce_kernel()
{
    const int b = blockIdx.y, n = blockIdx.x*256 + threadIdx.x;
    float s = 0.f;
    #pragma unroll
    for (int mt = 0; mt < 32; mt++) s += g_Lp[((size_t)b*32 + mt)*NN + n];
    g_Li[(size_t)b*NN + n] = 1.0f / s;
}

// reduce split-K x16 + softmax over d; writes f_c^T[d][c]; grid (256,4)
__global__ __launch_bounds__(256) void fcsoftmax_kernel()
{
    __shared__ float red[256];
    const int b = blockIdx.y, c = blockIdx.x, tid = threadIdx.x;
    float v = 0.f;
    #pragma unroll
    for (int ks = 0; ks < 16; ks++)
        v += g_FCP[(((size_t)b*16 + ks)*IC + c)*IC + tid];
    red[tid] = v; __syncthreads();
    for (int s = 128; s > 0; s >>= 1) {
        if (tid < s) red[tid] = fmaxf(red[tid], red[tid + s]);
        __syncthreads();
    }
    float m = red[0]; __syncthreads();
    float e = __expf(v - m);
    red[tid] = e; __syncthreads();
    for (int s = 128; s > 0; s >>= 1) {
        if (tid < s) red[tid] += red[tid + s];
        __syncthreads();
    }
    g_FC[(size_t)b*IC*IC + (size_t)tid*IC + c] = e / red[0];
}

// z = x + gs*(Ws@ys+b) + gc*(Wc@yc+b); grid (256,4)
__global__ __launch_bounds__(256) void zmix_kernel(
    const float* __restrict__ x,
    const float* __restrict__ Ws_w, const float* __restrict__ Ws_b,
    const float* __restrict__ Wc_w, const float* __restrict__ Wc_b,
    const float* __restrict__ gs, const float* __restrict__ gc,
    float* __restrict__ zout)
{
    __shared__ float sW[64][64];
    __shared__ float sD[64][65];
    const int b = blockIdx.y, p0 = blockIdx.x*64;
    const int tid = threadIdx.x, tx = tid & 63, ty = tid >> 6;
    float accs[16] = {}, accc[16] = {};
    #pragma unroll
    for (int l = 0; l < 16; l++) {
        int idx = l*256 + tid;
        sW[idx >> 6][idx & 63] = Ws_w[idx];
        int i = idx >> 6, px = idx & 63;
        int p = p0 + px, h = p >> 7, w = p & 127;
        int o = 4*i + (h >> 5), n = ((h & 31) << 7) | w;
        sD[i][px] = g_YS[((size_t)(b << 12) + n)*IC + o];
    }
    __syncthreads();
    #pragma unroll 4
    for (int i = 0; i < 64; i++) {
        float yv = sD[i][tx];
        #pragma unroll
        for (int k = 0; k < 16; k++) accs[k] += sW[16*ty + k][i]*yv;
    }
    __syncthreads();
    #pragma unroll
    for (int l = 0; l < 16; l++) {
        int idx = l*256 + tid;
        sW[idx >> 6][idx & 63] = Wc_w[idx];
        int i = idx >> 6, px = idx & 63;
        int p = p0 + px, h = p >> 7, w = p & 127;
        int n = (i << 6) + (h >> 1), d = ((h & 1) << 7) | w;
        sD[i][px] = g_YC[((size_t)(b << 12) + n)*IC + d];
    }
    __syncthreads();
    #pragma unroll 4
    for (int i = 0; i < 64; i++) {
        float cv = sD[i][tx];
        #pragma unroll
        for (int k = 0; k < 16; k++) accc[k] += sW[16*ty + k][i]*cv;
    }
    float gsv = gs[0], gcv = gc[0];
    int p = p0 + tx;
    #pragma unroll
    for (int k = 0; k < 16; k++) {
        int oc = 16*ty + k;
        size_t idx = (size_t)(b*64 + oc)*HW + p;
        float z = x[idx] + gsv*(accs[k] + Ws_b[oc]) + gcv*(accc[k] + Wc_b[oc]);
        g_Z[idx] = z;
        zout[idx] = z;
    }
}

// conv3x3 64->16 + relu, double-buffered; grid (4,16,4), block (32,8)
__global__ __launch_bounds__(256) void conv1_kernel(
    const float* __restrict__ m1w, const float* __restrict__ m1b)
{
    __shared__ float sw[16*64*9];
    __shared__ float st[2][10][36];
    const int b = blockIdx.z, h0 = blockIdx.y*8, w0 = blockIdx.x*32;
    const int tx = threadIdx.x, ty = threadIdx.y, tid = ty*32 + tx;
    for (int i = tid; i < 9216; i += 256) sw[i] = m1w[i];
    float acc[16];
    #pragma unroll
    for (int oc = 0; oc < 16; oc++) acc[oc] = m1b[oc];

    auto load_tile = [&](int ic, int buf) {
        const float* zp = g_Z + (size_t)(b*64 + ic)*HW;
        for (int l = tid; l < 340; l += 256) {
            int yy = l / 34, xx = l % 34;
            int hh = h0 - 1 + yy, ww = w0 - 1 + xx;
            st[buf][yy][xx] = (hh >= 0 && hh < 128 && ww >= 0 && ww < 128)
                              ? zp[hh*128 + ww] : 0.f;
        }
    };
    load_tile(0, 0);
    __syncthreads();
    for (int ic = 0; ic < 64; ic++) {
        if (ic + 1 < 64) load_tile(ic + 1, (ic + 1) & 1);
        const int cb = ic & 1;
        #pragma unroll
        for (int dy = 0; dy < 3; dy++)
            #pragma unroll
            for (int dx = 0; dx < 3; dx++) {
                float zv = st[cb][ty + dy][tx + dx];
                #pragma unroll
                for (int oc = 0; oc < 16; oc++)
                    acc[oc] += sw[(oc*64 + ic)*9 + dy*3 + dx]*zv;
            }
        __syncthreads();
    }
    int h = h0 + ty, w = w0 + tx;
    #pragma unroll
    for (int oc = 0; oc < 16; oc++)
        g_H[(size_t)(b*16 + oc)*HW + h*128 + w] = fmaxf(acc[oc], 0.f);
}

// conv3x3 16->1, double-buffered; grid (4,16,4), block (32,8)
__global__ __launch_bounds__(256) void conv2_kernel(
    const float* __restrict__ m2w, const float* __restrict__ m2b,
    float* __restrict__ out)
{
    __shared__ float sw[144];
    __shared__ float st[2][10][36];
    const int b = blockIdx.z, h0 = blockIdx.y*8, w0 = blockIdx.x*32;
    const int tx = threadIdx.x, ty = threadIdx.y, tid = ty*32 + tx;
    if (tid < 144) sw[tid] = m2w[tid];
    float acc = m2b[0];
    auto load_tile = [&](int ic, int buf) {
        const float* hp = g_H + (size_t)(b*16 + ic)*HW;
        for (int l = tid; l < 340; l += 256) {
            int yy = l / 34, xx = l % 34;
            int hh = h0 - 1 + yy, ww = w0 - 1 + xx;
            st[buf][yy][xx] = (hh >= 0 && hh < 128 && ww >= 0 && ww < 128)
                              ? hp[hh*128 + ww] : 0.f;
        }
    };
    load_tile(0, 0);
    __syncthreads();
    for (int ic = 0; ic < 16; ic++) {
        if (ic + 1 < 16) load_tile(ic + 1, (ic + 1) & 1);
        const int cb = ic & 1;
        #pragma unroll
        for (int dy = 0; dy < 3; dy++)
            #pragma unroll
            for (int dx = 0; dx < 3; dx++)
                acc += sw[ic*9 + dy*3 + dx]*st[cb][ty + dy][tx + dx];
        __syncthreads();
    }
    out[(size_t)b*HW + (h0 + ty)*128 + (w0 + tx)] = acc;
}

extern "C" void kernel_launch(void* const* d_in, const int* in_sizes, int n_in,
                              void* d_out, int out_size)
{
    const float* x    = (const float*)d_in[0];
    const float* g_w  = (const float*)d_in[1];
    const float* g_b  = (const float*)d_in[2];
    const float* th_w = (const float*)d_in[3];
    const float* th_b = (const float*)d_in[4];
    const float* ph_w = (const float*)d_in[5];
    const float* ph_b = (const float*)d_in[6];
    const float* Ws_w = (const float*)d_in[7];
    const float* Ws_b = (const float*)d_in[8];
    const float* Wc_w = (const float*)d_in[9];
    const float* Wc_b = (const float*)d_in[10];
    const float* gs   = (const float*)d_in[11];
    const float* gc   = (const float*)d_in[12];
    const float* m1w  = (const float*)d_in[13];
    const float* m1b  = (const float*)d_in[14];
    const float* m2w  = (const float*)d_in[15];
    const float* m2b  = (const float*)d_in[16];
    float* out = (float*)d_out;   // logit [4*16384] then z [4*64*16384]

    cudaFuncSetAttribute(wgemm, cudaFuncAttributeMaxDynamicSharedMemorySize, SMSZ);
    cudaFuncSetAttribute(proj_all, cudaFuncAttributeMaxDynamicSharedMemorySize, SMSZ);
    cudaFuncSetAttribute(bgemm, cudaFuncAttributeMaxDynamicSharedMemorySize, BSMSZ);
    cudaFuncSetAttribute(fcgemm_tn, cudaFuncAttributeMaxDynamicSharedMemorySize, TSMSZ);

    float *XT, *GN, *Lp, *Li, *YS, *FC, *YC;
    __nv_bfloat16 *Pb, *GXb, *THb, *PHb;
    cudaGetSymbolAddress((void**)&XT, g_XT);
    cudaGetSymbolAddress((void**)&THb, g_THb);
    cudaGetSymbolAddress((void**)&PHb, g_PHb);
    cudaGetSymbolAddress((void**)&GXb, g_GXb);
    cudaGetSymbolAddress((void**)&GN, g_GN);
    cudaGetSymbolAddress((void**)&Pb, g_Pb);
    cudaGetSymbolAddress((void**)&Lp, g_Lp);
    cudaGetSymbolAddress((void**)&Li, g_Li);
    cudaGetSymbolAddress((void**)&YS, g_YS);
    cudaGetSymbolAddress((void**)&FC, g_FC);
    cudaGetSymbolAddress((void**)&YC, g_YC);

    transpose_kernel<<<dim3(128, 8, 4), dim3(32, 8)>>>(x);

    // theta/phi/g_n [n][c] (fp32 + bf16 copies for theta/phi), one launch
    proj_all<<<dim3(32, 6, 4), 256, SMSZ>>>(th_w, ph_w, g_w, th_b, ph_b, g_b);
    // g [o][n] = g_w @ XT^T + bias(row), bf16 out
    wgemm<<<dim3(2, 32, 4), 256, SMSZ>>>(g_w, IC, 0,
        XT, IC, (size_t)NN*IC, GXb, NN, (size_t)IC*NN, IC, g_b, 1);

    fcgemm_tn<<<dim3(2, 2, 64), 128, TSMSZ>>>();
    fcsoftmax_kernel<<<dim3(256, 4), 256>>>();

    // Pb = exp(THb @ PHb^T) bf16 (m16n8k16), fused row partial sums
    bgemm<<<dim3(32, 32, 4), 256, BSMSZ>>>(THb, IC, (size_t)NN*IC,
        PHb, IC, (size_t)NN*IC, Pb, NN, (size_t)NN*NN, IC, nullptr, Lp, 2);
    lreduce_kernel<<<dim3(16, 4), 256>>>();
    // y_s = (Pb @ GXb^T) * Li[row], bf16 MMA
    bgemm<<<dim3(32, 2, 4), 256, BSMSZ>>>(Pb, NN, (size_t)NN*NN,
        GXb, NN, (size_t)IC*NN, YS, IC, (size_t)NN*IC, NN, Li, nullptr, 3);
    // y_c = GN @ (f_c^T)^T, fp32 (tf32 MMA)
    wgemm<<<dim3(32, 2, 4), 256, SMSZ>>>(GN, IC, (size_t)NN*IC,
        FC, IC, (size_t)IC*IC, YC, IC, (size_t)NN*IC, IC, nullptr, 4);

    zmix_kernel<<<dim3(256, 4), 256>>>(x, Ws_w, Ws_b, Wc_w, Wc_b, gs, gc, out + 65536);
    conv1_kernel<<<dim3(4, 16, 4), dim3(32, 8)>>>(m1w, m1b);
    conv2_kernel<<<dim3(4, 16, 4), dim3(32, 8)>>>(m2w, m2b, out);
}